// round 1
// baseline (speedup 1.0000x reference)
#include <cuda_runtime.h>
#include <math.h>

#define NWAY 5
#define BB 4
#define CC 64
#define HWN 25
#define MS 125      // K_SHOT * h * w
#define MU 2500     // u * h * w
#define QQ 75
#define COLS 625    // NWAY * MS
#define MTOT 2625   // MS + MU

// ---------------- scratch (static device allocations only) ----------------
__device__ float g_sup_n[BB*COLS*CC];            // [b][col=w*125+n][c], l2-normalized support
__device__ float g_unl_n[BB*MU*CC];              // [b][m][c], l2-normalized unlabeled
__device__ unsigned long long g_rowbest[BB*MU];  // per (b,m): packed (val,col) argmax over 625 cols
__device__ unsigned long long g_colbest[BB*COLS];// per (b,col): packed (val,m) argmax over 2500 m
__device__ int g_sel[BB*NWAY*MU];                // compacted m-indices per (b,way)
__device__ int g_count[BB*NWAY];
__device__ int g_L[1];

// monotone float ordering map (handles negatives exactly)
__device__ __forceinline__ unsigned fmap(float f){
    unsigned b=__float_as_uint(f);
    return (b&0x80000000u)? ~b : (b|0x80000000u);
}
__device__ __forceinline__ float funmap(unsigned u){
    return (u&0x80000000u)? __uint_as_float(u^0x80000000u) : __uint_as_float(~u);
}
// max-value, min-index-on-tie key (matches jnp first-occurrence argmax)
__device__ __forceinline__ unsigned long long packkey(float v, unsigned idx){
    return (((unsigned long long)fmap(v))<<32) | (unsigned long long)(0xFFFFFFFFu - idx);
}

// ---------------- K0: init ----------------
__global__ void k_init(float* out, int out_size){
    int i = blockIdx.x*blockDim.x + threadIdx.x;
    int stride = gridDim.x*blockDim.x;
    for (int t=i; t<BB*MU;   t+=stride) g_rowbest[t]=0ULL;
    for (int t=i; t<BB*COLS; t+=stride) g_colbest[t]=0ULL;
    for (int t=i; t<out_size; t+=stride) out[t]=0.f;
}

// ---------------- K1: normalize support -> g_sup_n ----------------
__global__ void k_norm_sup(const float* __restrict__ x){
    int s = blockIdx.x;            // 0..99 = b*25 + (w*5+k)
    int b = s/25, sk = s%25;
    __shared__ float tile[1600];   // [c][hw]
    __shared__ float inv[HWN];
    const float* in = x + (size_t)s*1600;
    for (int t=threadIdx.x; t<1600; t+=256) tile[t]=in[t];
    __syncthreads();
    if (threadIdx.x < HWN){
        float a=0.f;
        for (int c=0;c<CC;++c){ float v=tile[c*HWN+threadIdx.x]; a=fmaf(v,v,a); }
        inv[threadIdx.x] = 1.0f / fmaxf(sqrtf(a), 1e-12f);
    }
    __syncthreads();
    int w = sk/5, k = sk%5;
    float* outp = g_sup_n + (size_t)(b*COLS + w*MS + k*25)*CC;
    for (int o=threadIdx.x;o<1600;o+=256){
        int hw=o>>6, c=o&63;
        outp[o]=tile[c*HWN+hw]*inv[hw];
    }
}

// ---------------- K2: normalize unlabeled -> g_unl_n ----------------
__global__ void k_norm_unl(const float* __restrict__ x){
    int s = blockIdx.x;            // 0..399 = b*100 + u
    int b = s/100, u = s%100;
    __shared__ float tile[1600];
    __shared__ float inv[HWN];
    const float* in = x + (size_t)s*1600;
    for (int t=threadIdx.x; t<1600; t+=256) tile[t]=in[t];
    __syncthreads();
    if (threadIdx.x < HWN){
        float a=0.f;
        for (int c=0;c<CC;++c){ float v=tile[c*HWN+threadIdx.x]; a=fmaf(v,v,a); }
        inv[threadIdx.x] = 1.0f / fmaxf(sqrtf(a), 1e-12f);
    }
    __syncthreads();
    float* outp = g_unl_n + (size_t)(b*MU + u*25)*CC;
    for (int o=threadIdx.x;o<1600;o+=256){
        int hw=o>>6, c=o&63;
        outp[o]=tile[c*HWN+hw]*inv[hw];
    }
}

// ---------------- K3: u2s cosine sims + packed row/col argmax ----------------
// warp = (b, colgroup cg in [0,20), mchunk mc in [0,10)); lane -> one of 32 cols
__global__ void k_u2s(){
    int gw = blockIdx.x*8 + (threadIdx.x>>5);   // 0..799
    int lane = threadIdx.x & 31;
    int b = gw/200; int r = gw%200; int cg = r/10; int mc = r%10;
    int col = cg*32 + lane;
    bool valid = col < COLS;
    float sv[CC];
    const float4* sp = reinterpret_cast<const float4*>(g_sup_n + (size_t)(b*COLS + (valid?col:0))*CC);
    #pragma unroll
    for (int i=0;i<16;++i){
        float4 v = valid ? sp[i] : make_float4(0.f,0.f,0.f,0.f);
        sv[4*i]=v.x; sv[4*i+1]=v.y; sv[4*i+2]=v.z; sv[4*i+3]=v.w;
    }
    unsigned long long ckbest = 0ULL;
    int m0 = mc*250;
    for (int m=m0; m<m0+250; ++m){
        const float* up = g_unl_n + (size_t)(b*MU + m)*CC;
        float u0 = up[lane], u1 = up[32+lane];
        float acc = 0.f;
        #pragma unroll
        for (int c=0;c<32;++c) acc = fmaf(sv[c],    __shfl_sync(0xffffffffu,u0,c), acc);
        #pragma unroll
        for (int c=0;c<32;++c) acc = fmaf(sv[32+c], __shfl_sync(0xffffffffu,u1,c), acc);
        unsigned long long rk = valid ? packkey(acc,(unsigned)col) : 0ULL;
        #pragma unroll
        for (int off=16;off>=1;off>>=1){
            unsigned long long o = __shfl_xor_sync(0xffffffffu, rk, off);
            if (o>rk) rk=o;
        }
        if (lane==0) atomicMax(&g_rowbest[b*MU+m], rk);
        if (valid){
            unsigned long long ck = packkey(acc,(unsigned)m);
            if (ck>ckbest) ckbest=ck;
        }
    }
    if (valid) atomicMax(&g_colbest[b*COLS+col], ckbest);
}

// ---------------- K4: umask + stable stream compaction per (b,way) ----------------
__global__ void k_compact(){
    int bw = blockIdx.x; int b = bw/NWAY, w = bw%NWAY;
    int tid = threadIdx.x, lane = tid&31, wid = tid>>5;
    __shared__ int wsum[8], woff[8], sbase;
    if (tid==0) sbase=0;
    __syncthreads();
    for (int chunk=0; chunk<10; ++chunk){
        int m = chunk*256 + tid;
        bool flag = false;
        if (m < MU){
            unsigned long long rb = g_rowbest[b*MU+m];
            unsigned col = 0xFFFFFFFFu - (unsigned)(rb & 0xFFFFFFFFu);
            if ((int)(col/MS) == w){
                unsigned long long cb = g_colbest[b*COLS+col];
                unsigned mm = 0xFFFFFFFFu - (unsigned)(cb & 0xFFFFFFFFu);
                flag = (mm == (unsigned)m);    // mutual nearest neighbor
            }
        }
        unsigned bal = __ballot_sync(0xffffffffu, flag);
        if (lane==0) wsum[wid] = __popc(bal);
        __syncthreads();
        if (tid==0){
            int run=sbase;
            for (int i=0;i<8;++i){ woff[i]=run; run+=wsum[i]; }
            sbase=run;
        }
        __syncthreads();
        if (flag){
            int pos = woff[wid] + __popc(bal & ((1u<<lane)-1u));
            g_sel[(b*NWAY+w)*MU + pos] = m;
        }
        __syncthreads();
    }
    if (tid==0) g_count[b*NWAY+w] = sbase;
}

// ---------------- K5: L = max count ----------------
__global__ void k_maxL(){
    int t = threadIdx.x;
    int v = (t<BB*NWAY) ? g_count[t] : 0;
    #pragma unroll
    for (int off=16;off>=1;off>>=1) v = max(v, __shfl_xor_sync(0xffffffffu,v,off));
    if (t==0) g_L[0]=v;
}

// ---------------- K6: fused query sim / mutual mask / CE loss ----------------
__global__ void k_sim(const float* __restrict__ qx, const int* __restrict__ qy,
                      float* __restrict__ out){
    int q = blockIdx.x, b = blockIdx.y;
    int tid = threadIdx.x, lane = tid&31;
    __shared__ __align__(16) float qn_s[HWN*CC];     // [mq][c], normalized query
    __shared__ float inv[HWN];
    __shared__ unsigned long long rowq[NWAY*HWN];    // packed per-(way,mq) best over cols
    __shared__ unsigned char colmq[NWAY*MTOT];       // per-column argmax over mq
    __shared__ int cnt_s[NWAY];
    __shared__ int sL;

    if (tid < NWAY*HWN) rowq[tid]=0ULL;
    if (tid < NWAY) cnt_s[tid]=g_count[b*NWAY+tid];
    if (tid==0) sL = g_L[0];

    const float* in = qx + (size_t)(b*QQ+q)*1600;
    for (int t=tid; t<1600; t+=256){
        int c=t/HWN, hw=t%HWN;
        qn_s[hw*CC+c]=in[t];
    }
    __syncthreads();
    if (tid < HWN){
        float a=0.f;
        for (int c=0;c<CC;++c){ float v=qn_s[tid*CC+c]; a=fmaf(v,v,a); }
        inv[tid] = 1.0f / fmaxf(sqrtf(a), 1e-12f);
    }
    __syncthreads();
    for (int t=tid;t<1600;t+=256) qn_s[t]*=inv[t>>6];
    __syncthreads();

    const float4* qn4 = reinterpret_cast<const float4*>(qn_s);

    for (int w=0; w<NWAY; ++w){
        int cw = cnt_s[w];
        int wl = MS + cw;
        unsigned long long wb[HWN];
        #pragma unroll
        for (int i=0;i<HWN;++i) wb[i]=0ULL;

        for (int j=tid; j<wl; j+=256){
            const float* vp;
            if (j < MS) vp = g_sup_n + (size_t)(b*COLS + w*MS + j)*CC;
            else        vp = g_unl_n + (size_t)(b*MU + g_sel[(b*NWAY+w)*MU + (j-MS)])*CC;
            const float4* vp4 = reinterpret_cast<const float4*>(vp);
            float acc[HWN];
            #pragma unroll
            for (int i=0;i<HWN;++i) acc[i]=0.f;
            #pragma unroll 4
            for (int c4=0;c4<16;++c4){
                float4 v = vp4[c4];
                #pragma unroll
                for (int mq=0;mq<HWN;++mq){
                    float4 a4 = qn4[mq*16+c4];
                    acc[mq]=fmaf(a4.x,v.x,fmaf(a4.y,v.y,fmaf(a4.z,v.z,fmaf(a4.w,v.w,acc[mq]))));
                }
            }
            unsigned gcol = (unsigned)(w*MTOT + j);
            float best=-1e30f; int bmq=0;
            #pragma unroll
            for (int mq=0;mq<HWN;++mq){
                float t = fmaf(acc[mq],0.5f,0.5f);   // (cos+1)*0.5
                acc[mq]=t;
                if (t>best){best=t;bmq=mq;}
            }
            colmq[w*MTOT+j]=(unsigned char)bmq;
            #pragma unroll
            for (int mq=0;mq<HWN;++mq){
                unsigned long long k = packkey(acc[mq], gcol);
                if (k>wb[mq]) wb[mq]=k;
            }
        }
        // warp reduce, then one atomic per (warp, way, mq)
        #pragma unroll
        for (int mq=0;mq<HWN;++mq){
            unsigned long long v=wb[mq];
            #pragma unroll
            for (int off=16;off>=1;off>>=1){
                unsigned long long o=__shfl_xor_sync(0xffffffffu,v,off);
                if (o>v) v=o;
            }
            if (lane==0) atomicMax(&rowq[w*HWN+mq], v);
        }
    }
    __syncthreads();

    if (tid < 32){
        float rmx[NWAY]={0.f,0.f,0.f,0.f,0.f};
        unsigned long long qb=0ULL;
        float maskv=0.f;
        if (lane < HWN){
            #pragma unroll
            for (int w=0;w<NWAY;++w){
                unsigned long long r = rowq[w*HWN+lane];
                int cw=cnt_s[w];
                if (cw < sL){
                    // first all-zero pad column of this way: sim = 0.5 exactly, colargmax mq=0
                    unsigned long long pk = packkey(0.5f,(unsigned)(w*MTOT+MS+cw));
                    if (pk>r) r=pk;
                }
                rmx[w]=funmap((unsigned)(r>>32));
                if (r>qb) qb=r;
            }
            unsigned gcol = 0xFFFFFFFFu - (unsigned)(qb & 0xFFFFFFFFu);
            int w_ = (int)(gcol / MTOT), j_ = (int)(gcol % MTOT);
            int amq = (j_ < MS + cnt_s[w_]) ? (int)colmq[w_*MTOT+j_] : 0;
            maskv = (amq==lane) ? 1.f : 0.f;
        }
        float qv[NWAY];
        #pragma unroll
        for (int w=0;w<NWAY;++w){
            float t = (lane<HWN) ? rmx[w]*maskv : 0.f;
            #pragma unroll
            for (int off=16;off>=1;off>>=1) t += __shfl_xor_sync(0xffffffffu,t,off);
            qv[w]=t;
        }
        if (lane==0){
            int y = qy[b*QQ+q];
            float mx=qv[0];
            #pragma unroll
            for (int w=1;w<NWAY;++w) mx=fmaxf(mx,qv[w]);
            float se=0.f;
            #pragma unroll
            for (int w=0;w<NWAY;++w) se += expf(qv[w]-mx);
            float li = mx + logf(se) - qv[y];     // -log softmax[y]
            atomicAdd(out, li*(1.0f/(float)(BB*QQ)));
        }
    }
}

// ---------------- launch ----------------
extern "C" void kernel_launch(void* const* d_in, const int* in_sizes, int n_in,
                              void* d_out, int out_size) {
    const float* sup = nullptr;
    const float* qx  = nullptr;
    const float* ux  = nullptr;
    const int*   qy  = nullptr;
    for (int i=0;i<n_in;++i){
        switch (in_sizes[i]){
            case 160000: sup = (const float*)d_in[i]; break; // support_xf 4*25*64*25
            case 480000: qx  = (const float*)d_in[i]; break; // query_xf   4*75*64*25
            case 640000: ux  = (const float*)d_in[i]; break; // unlabeled  4*100*64*25
            case 300:    qy  = (const int*)d_in[i];   break; // query_y
            default: break;                                  // support_y unused
        }
    }
    float* out = (float*)d_out;
    k_init<<<64,256>>>(out, out_size);
    k_norm_sup<<<100,256>>>(sup);
    k_norm_unl<<<400,256>>>(ux);
    k_u2s<<<100,256>>>();
    k_compact<<<BB*NWAY,256>>>();
    k_maxL<<<1,32>>>();
    k_sim<<<dim3(QQ,BB),256>>>(qx, qy, out);
}

// round 2
// speedup vs baseline: 1.7797x; 1.7797x over previous
#include <cuda_runtime.h>
#include <math.h>

#define NWAY 5
#define BB 4
#define CC 64
#define HWN 25
#define MS 125      // K_SHOT * h * w
#define MU 2500     // u * h * w
#define QQ 75
#define COLS 625    // NWAY * MS
#define MTOT 2625   // MS + MU
#define COLP 640    // padded cols for transposed support
#define MUP 2560    // padded m for transposed unlabeled

// ---------------- scratch (static device allocations only) ----------------
__device__ float g_sup_n[BB*COLS*CC];            // [b][col][c], l2-normalized support
__device__ float g_unl_n[BB*MU*CC];              // [b][m][c],  l2-normalized unlabeled
__device__ float g_sup_t[BB*CC*COLP];            // [b][c][col] transposed (pad zeroed)
__device__ float g_unl_t[BB*CC*MUP];             // [b][c][m]   transposed (pad zeroed)
__device__ unsigned long long g_rowbest[BB*MU];  // per (b,m): packed (val,col) argmax
__device__ unsigned long long g_colbest[BB*COLS];// per (b,col): packed (val,m) argmax
__device__ int g_sel[BB*NWAY*MU];                // compacted m-indices per (b,way)
__device__ int g_count[BB*NWAY];
__device__ int g_L[1];

// monotone float ordering map (handles negatives exactly)
__device__ __forceinline__ unsigned fmap(float f){
    unsigned b=__float_as_uint(f);
    return (b&0x80000000u)? ~b : (b|0x80000000u);
}
__device__ __forceinline__ float funmap(unsigned u){
    return (u&0x80000000u)? __uint_as_float(u^0x80000000u) : __uint_as_float(~u);
}
// max-value, min-index-on-tie key (matches jnp first-occurrence argmax)
__device__ __forceinline__ unsigned long long packkey(float v, unsigned idx){
    return (((unsigned long long)fmap(v))<<32) | (unsigned long long)(0xFFFFFFFFu - idx);
}

// ---------------- K0: init ----------------
__global__ void k_init(float* out, int out_size){
    int i = blockIdx.x*blockDim.x + threadIdx.x;
    int stride = gridDim.x*blockDim.x;
    for (int t=i; t<BB*MU;   t+=stride) g_rowbest[t]=0ULL;
    for (int t=i; t<BB*COLS; t+=stride) g_colbest[t]=0ULL;
    // zero pad regions of transposed tensors
    for (int t=i; t<BB*CC*(COLP-COLS); t+=stride){
        int bc=t/(COLP-COLS), p=t%(COLP-COLS);
        g_sup_t[(size_t)bc*COLP + COLS + p]=0.f;
    }
    for (int t=i; t<BB*CC*(MUP-MU); t+=stride){
        int bc=t/(MUP-MU), p=t%(MUP-MU);
        g_unl_t[(size_t)bc*MUP + MU + p]=0.f;
    }
    for (int t=i; t<out_size; t+=stride) out[t]=0.f;
}

// ---------------- K1: normalize support -> g_sup_n + g_sup_t ----------------
__global__ void k_norm_sup(const float* __restrict__ x){
    int s = blockIdx.x;            // 0..99 = b*25 + (w*5+k)
    int b = s/25, sk = s%25;
    __shared__ float tile[1600];   // [c][hw]
    __shared__ float inv[HWN];
    const float* in = x + (size_t)s*1600;
    for (int t=threadIdx.x; t<1600; t+=256) tile[t]=in[t];
    __syncthreads();
    if (threadIdx.x < HWN){
        float a=0.f;
        for (int c=0;c<CC;++c){ float v=tile[c*HWN+threadIdx.x]; a=fmaf(v,v,a); }
        inv[threadIdx.x] = 1.0f / fmaxf(sqrtf(a), 1e-12f);
    }
    __syncthreads();
    int w = sk/5, k = sk%5;
    int colbase = w*MS + k*25;
    float* outp = g_sup_n + (size_t)(b*COLS + colbase)*CC;
    float* outt = g_sup_t + (size_t)b*CC*COLP + colbase;
    for (int o=threadIdx.x;o<1600;o+=256){
        int hw=o>>6, c=o&63;
        outp[o]=tile[c*HWN+hw]*inv[hw];
    }
    for (int o=threadIdx.x;o<1600;o+=256){
        int c=o/HWN, hw=o%HWN;
        outt[(size_t)c*COLP + hw]=tile[o]*inv[hw];
    }
}

// ---------------- K2: normalize unlabeled -> g_unl_n + g_unl_t ----------------
__global__ void k_norm_unl(const float* __restrict__ x){
    int s = blockIdx.x;            // 0..399 = b*100 + u
    int b = s/100, u = s%100;
    __shared__ float tile[1600];
    __shared__ float inv[HWN];
    const float* in = x + (size_t)s*1600;
    for (int t=threadIdx.x; t<1600; t+=256) tile[t]=in[t];
    __syncthreads();
    if (threadIdx.x < HWN){
        float a=0.f;
        for (int c=0;c<CC;++c){ float v=tile[c*HWN+threadIdx.x]; a=fmaf(v,v,a); }
        inv[threadIdx.x] = 1.0f / fmaxf(sqrtf(a), 1e-12f);
    }
    __syncthreads();
    float* outp = g_unl_n + (size_t)(b*MU + u*25)*CC;
    float* outt = g_unl_t + (size_t)b*CC*MUP + u*25;
    for (int o=threadIdx.x;o<1600;o+=256){
        int hw=o>>6, c=o&63;
        outp[o]=tile[c*HWN+hw]*inv[hw];
    }
    for (int o=threadIdx.x;o<1600;o+=256){
        int c=o/HWN, hw=o%HWN;
        outt[(size_t)c*MUP + hw]=tile[o]*inv[hw];
    }
}

// ---------------- K3: u2s as smem-tiled GEMM + packed row/col argmax ----------
// block: 64 cols x 128 m, K=64 fully resident. 256 threads, 4x8 register tile.
__global__ void __launch_bounds__(256) k_u2s(){
    __shared__ float4 s4[64*16];   // [c][16 f4] = 64 cols  (16KB)
    __shared__ float4 u4[64*32];   // [c][32 f4] = 128 m    (32KB)  total 48KB
    int mt = blockIdx.x;           // 0..19
    int ct = blockIdx.y;           // 0..9
    int b  = blockIdx.z;
    int tid = threadIdx.x;
    int lane = tid & 31;

    const float4* gs4 = reinterpret_cast<const float4*>(g_sup_t) + (size_t)b*(CC*COLP/4) + ct*16;
    for (int t=tid; t<64*16; t+=256){
        int c=t>>4, x=t&15;
        s4[t] = gs4[(size_t)c*(COLP/4) + x];
    }
    const float4* gu4 = reinterpret_cast<const float4*>(g_unl_t) + (size_t)b*(CC*MUP/4) + mt*32;
    for (int t=tid; t<64*32; t+=256){
        int c=t>>5, x=t&31;
        u4[t] = gu4[(size_t)c*(MUP/4) + x];
    }
    __syncthreads();

    int i = tid & 15;              // col quad -> cols ct*64 + i*4 + j
    int g = tid >> 4;              // m oct    -> ms   mt*128 + g*8 + k
    float acc[32];
    #pragma unroll
    for (int t=0;t<32;++t) acc[t]=0.f;

    #pragma unroll 4
    for (int c=0;c<64;++c){
        float4 a  = s4[c*16 + i];
        float4 b0 = u4[c*32 + 2*g];
        float4 b1 = u4[c*32 + 2*g + 1];
        float av[4]={a.x,a.y,a.z,a.w};
        float bv[8]={b0.x,b0.y,b0.z,b0.w,b1.x,b1.y,b1.z,b1.w};
        #pragma unroll
        for (int j=0;j<4;++j)
            #pragma unroll
            for (int k=0;k<8;++k)
                acc[j*8+k]=fmaf(av[j],bv[k],acc[j*8+k]);
    }

    int col0 = ct*64 + i*4;
    int m0   = mt*128 + g*8;

    // per-thread reductions
    unsigned long long rk[8], ck[4];
    #pragma unroll
    for (int k=0;k<8;++k) rk[k]=0ULL;
    #pragma unroll
    for (int j=0;j<4;++j) ck[j]=0ULL;
    #pragma unroll
    for (int j=0;j<4;++j){
        bool vc = (col0+j) < COLS;
        #pragma unroll
        for (int k=0;k<8;++k){
            if (vc){
                unsigned long long kk = packkey(acc[j*8+k], (unsigned)(col0+j));
                if (kk>rk[k]) rk[k]=kk;
            }
            if ((m0+k) < MU){
                unsigned long long kk2 = packkey(acc[j*8+k], (unsigned)(m0+k));
                if (kk2>ck[j]) ck[j]=kk2;
            }
        }
    }
    // row (per-m) reduce over i within each 16-lane half, then global atomic
    #pragma unroll
    for (int k=0;k<8;++k){
        unsigned long long v=rk[k];
        #pragma unroll
        for (int off=8;off>=1;off>>=1){
            unsigned long long o=__shfl_xor_sync(0xffffffffu,v,off);
            if (o>v) v=o;
        }
        rk[k]=v;
    }
    if ((lane&15)==0){
        #pragma unroll
        for (int k=0;k<8;++k)
            if ((m0+k)<MU && rk[k])
                atomicMax(&g_rowbest[(size_t)b*MU + m0 + k], rk[k]);
    }
    // col (per-col) reduce: combine the two g-halves in-warp, then smem atomics
    #pragma unroll
    for (int j=0;j<4;++j){
        unsigned long long o=__shfl_xor_sync(0xffffffffu,ck[j],16);
        if (o>ck[j]) ck[j]=o;
    }
    __syncthreads();                      // done reading s4; reuse as sm_col
    unsigned long long* sm_col = reinterpret_cast<unsigned long long*>(s4);
    if (tid < 64) sm_col[tid]=0ULL;
    __syncthreads();
    if (lane < 16){
        #pragma unroll
        for (int j=0;j<4;++j)
            if (ck[j]) atomicMax(&sm_col[i*4+j], ck[j]);
    }
    __syncthreads();
    if (tid < 64 && (ct*64+tid) < COLS && sm_col[tid])
        atomicMax(&g_colbest[(size_t)b*COLS + ct*64 + tid], sm_col[tid]);
}

// ---------------- K4: umask + stable stream compaction per (b,way) ----------------
__global__ void k_compact(){
    int bw = blockIdx.x; int b = bw/NWAY, w = bw%NWAY;
    int tid = threadIdx.x, lane = tid&31, wid = tid>>5;
    __shared__ int wsum[8], woff[8], sbase;
    if (tid==0) sbase=0;
    __syncthreads();
    for (int chunk=0; chunk<10; ++chunk){
        int m = chunk*256 + tid;
        bool flag = false;
        if (m < MU){
            unsigned long long rb = g_rowbest[b*MU+m];
            unsigned col = 0xFFFFFFFFu - (unsigned)(rb & 0xFFFFFFFFu);
            if ((int)(col/MS) == w){
                unsigned long long cb = g_colbest[b*COLS+col];
                unsigned mm = 0xFFFFFFFFu - (unsigned)(cb & 0xFFFFFFFFu);
                flag = (mm == (unsigned)m);    // mutual nearest neighbor
            }
        }
        unsigned bal = __ballot_sync(0xffffffffu, flag);
        if (lane==0) wsum[wid] = __popc(bal);
        __syncthreads();
        if (tid==0){
            int run=sbase;
            for (int i=0;i<8;++i){ woff[i]=run; run+=wsum[i]; }
            sbase=run;
        }
        __syncthreads();
        if (flag){
            int pos = woff[wid] + __popc(bal & ((1u<<lane)-1u));
            g_sel[(b*NWAY+w)*MU + pos] = m;
        }
        __syncthreads();
    }
    if (tid==0) g_count[b*NWAY+w] = sbase;
}

// ---------------- K5: L = max count ----------------
__global__ void k_maxL(){
    int t = threadIdx.x;
    int v = (t<BB*NWAY) ? g_count[t] : 0;
    #pragma unroll
    for (int off=16;off>=1;off>>=1) v = max(v, __shfl_xor_sync(0xffffffffu,v,off));
    if (t==0) g_L[0]=v;
}

// ---------------- K6: fused query sim / mutual mask / CE loss ----------------
__global__ void k_sim(const float* __restrict__ qx, const int* __restrict__ qy,
                      float* __restrict__ out){
    int q = blockIdx.x, b = blockIdx.y;
    int tid = threadIdx.x, lane = tid&31;
    __shared__ __align__(16) float qn_s[HWN*CC];     // [mq][c], normalized query
    __shared__ float inv[HWN];
    __shared__ unsigned long long rowq[NWAY*HWN];    // packed per-(way,mq) best over cols
    __shared__ unsigned char colmq[NWAY*MTOT];       // per-column argmax over mq
    __shared__ int cnt_s[NWAY];
    __shared__ int sL;

    if (tid < NWAY*HWN) rowq[tid]=0ULL;
    if (tid < NWAY) cnt_s[tid]=g_count[b*NWAY+tid];
    if (tid==0) sL = g_L[0];

    const float* in = qx + (size_t)(b*QQ+q)*1600;
    for (int t=tid; t<1600; t+=256){
        int c=t/HWN, hw=t%HWN;
        qn_s[hw*CC+c]=in[t];
    }
    __syncthreads();
    if (tid < HWN){
        float a=0.f;
        for (int c=0;c<CC;++c){ float v=qn_s[tid*CC+c]; a=fmaf(v,v,a); }
        inv[tid] = 1.0f / fmaxf(sqrtf(a), 1e-12f);
    }
    __syncthreads();
    for (int t=tid;t<1600;t+=256) qn_s[t]*=inv[t>>6];
    __syncthreads();

    const float4* qn4 = reinterpret_cast<const float4*>(qn_s);

    for (int w=0; w<NWAY; ++w){
        int cw = cnt_s[w];
        int wl = MS + cw;
        unsigned long long wb[HWN];
        #pragma unroll
        for (int i=0;i<HWN;++i) wb[i]=0ULL;

        for (int j=tid; j<wl; j+=256){
            const float* vp;
            if (j < MS) vp = g_sup_n + (size_t)(b*COLS + w*MS + j)*CC;
            else        vp = g_unl_n + (size_t)(b*MU + g_sel[(b*NWAY+w)*MU + (j-MS)])*CC;
            const float4* vp4 = reinterpret_cast<const float4*>(vp);
            float acc[HWN];
            #pragma unroll
            for (int i=0;i<HWN;++i) acc[i]=0.f;
            #pragma unroll 4
            for (int c4=0;c4<16;++c4){
                float4 v = vp4[c4];
                #pragma unroll
                for (int mq=0;mq<HWN;++mq){
                    float4 a4 = qn4[mq*16+c4];
                    acc[mq]=fmaf(a4.x,v.x,fmaf(a4.y,v.y,fmaf(a4.z,v.z,fmaf(a4.w,v.w,acc[mq]))));
                }
            }
            unsigned gcol = (unsigned)(w*MTOT + j);
            float best=-1e30f; int bmq=0;
            #pragma unroll
            for (int mq=0;mq<HWN;++mq){
                float t = fmaf(acc[mq],0.5f,0.5f);   // (cos+1)*0.5
                acc[mq]=t;
                if (t>best){best=t;bmq=mq;}
            }
            colmq[w*MTOT+j]=(unsigned char)bmq;
            #pragma unroll
            for (int mq=0;mq<HWN;++mq){
                unsigned long long k = packkey(acc[mq], gcol);
                if (k>wb[mq]) wb[mq]=k;
            }
        }
        // warp reduce, then one atomic per (warp, way, mq)
        #pragma unroll
        for (int mq=0;mq<HWN;++mq){
            unsigned long long v=wb[mq];
            #pragma unroll
            for (int off=16;off>=1;off>>=1){
                unsigned long long o=__shfl_xor_sync(0xffffffffu,v,off);
                if (o>v) v=o;
            }
            if (lane==0) atomicMax(&rowq[w*HWN+mq], v);
        }
    }
    __syncthreads();

    if (tid < 32){
        float rmx[NWAY]={0.f,0.f,0.f,0.f,0.f};
        unsigned long long qb=0ULL;
        float maskv=0.f;
        if (lane < HWN){
            #pragma unroll
            for (int w=0;w<NWAY;++w){
                unsigned long long r = rowq[w*HWN+lane];
                int cw=cnt_s[w];
                if (cw < sL){
                    // first all-zero pad column of this way: sim = 0.5 exactly, colargmax mq=0
                    unsigned long long pk = packkey(0.5f,(unsigned)(w*MTOT+MS+cw));
                    if (pk>r) r=pk;
                }
                rmx[w]=funmap((unsigned)(r>>32));
                if (r>qb) qb=r;
            }
            unsigned gcol = 0xFFFFFFFFu - (unsigned)(qb & 0xFFFFFFFFu);
            int w_ = (int)(gcol / MTOT), j_ = (int)(gcol % MTOT);
            int amq = (j_ < MS + cnt_s[w_]) ? (int)colmq[w_*MTOT+j_] : 0;
            maskv = (amq==lane) ? 1.f : 0.f;
        }
        float qv[NWAY];
        #pragma unroll
        for (int w=0;w<NWAY;++w){
            float t = (lane<HWN) ? rmx[w]*maskv : 0.f;
            #pragma unroll
            for (int off=16;off>=1;off>>=1) t += __shfl_xor_sync(0xffffffffu,t,off);
            qv[w]=t;
        }
        if (lane==0){
            int y = qy[b*QQ+q];
            float mx=qv[0];
            #pragma unroll
            for (int w=1;w<NWAY;++w) mx=fmaxf(mx,qv[w]);
            float se=0.f;
            #pragma unroll
            for (int w=0;w<NWAY;++w) se += expf(qv[w]-mx);
            float li = mx + logf(se) - qv[y];     // -log softmax[y]
            atomicAdd(out, li*(1.0f/(float)(BB*QQ)));
        }
    }
}

// ---------------- launch ----------------
extern "C" void kernel_launch(void* const* d_in, const int* in_sizes, int n_in,
                              void* d_out, int out_size) {
    const float* sup = nullptr;
    const float* qx  = nullptr;
    const float* ux  = nullptr;
    const int*   qy  = nullptr;
    for (int i=0;i<n_in;++i){
        switch (in_sizes[i]){
            case 160000: sup = (const float*)d_in[i]; break; // support_xf 4*25*64*25
            case 480000: qx  = (const float*)d_in[i]; break; // query_xf   4*75*64*25
            case 640000: ux  = (const float*)d_in[i]; break; // unlabeled  4*100*64*25
            case 300:    qy  = (const int*)d_in[i];   break; // query_y
            default: break;                                  // support_y unused
        }
    }
    float* out = (float*)d_out;
    k_init<<<64,256>>>(out, out_size);
    k_norm_sup<<<100,256>>>(sup);
    k_norm_unl<<<400,256>>>(ux);
    k_u2s<<<dim3(20,10,BB),256>>>();
    k_compact<<<BB*NWAY,256>>>();
    k_maxL<<<1,32>>>();
    k_sim<<<dim3(QQ,BB),256>>>(qx, qy, out);
}

// round 3
// speedup vs baseline: 2.0433x; 1.1481x over previous
#include <cuda_runtime.h>
#include <math.h>

#define NWAY 5
#define BB 4
#define CC 64
#define HWN 25
#define MS 125      // K_SHOT * h * w
#define MU 2500     // u * h * w
#define QQ 75
#define COLS 625    // NWAY * MS
#define MTOT 2625   // MS + MU
#define COLP 640    // padded cols for transposed support
#define MUP 2560    // padded m for transposed unlabeled

// ---------------- scratch (static device allocations only) ----------------
__device__ float g_sup_n[BB*COLS*CC];            // [b][col][c], l2-normalized support
__device__ float g_unl_n[BB*MU*CC];              // [b][m][c],  l2-normalized unlabeled
__device__ float g_q_n[BB*QQ*HWN*CC];            // [b][q][mq][c], normalized query
__device__ float g_sup_t[BB*CC*COLP];            // [b][c][col] transposed (pad zeroed)
__device__ float g_unl_t[BB*CC*MUP];             // [b][c][m]   transposed (pad zeroed)
__device__ unsigned long long g_rowbest[BB*MU];  // per (b,m): packed (val,col) argmax
__device__ unsigned long long g_colbest[BB*COLS];// per (b,col): packed (val,m) argmax
__device__ int g_sel[BB*NWAY*MU];                // compacted m-indices per (b,way)
__device__ int g_count[BB*NWAY];
__device__ int g_L[1];

// monotone float ordering map (handles negatives exactly)
__device__ __forceinline__ unsigned fmap(float f){
    unsigned b=__float_as_uint(f);
    return (b&0x80000000u)? ~b : (b|0x80000000u);
}
__device__ __forceinline__ float funmap(unsigned u){
    return (u&0x80000000u)? __uint_as_float(u^0x80000000u) : __uint_as_float(~u);
}
// max-value, min-index-on-tie key (matches jnp first-occurrence argmax)
__device__ __forceinline__ unsigned long long packkey(float v, unsigned idx){
    return (((unsigned long long)fmap(v))<<32) | (unsigned long long)(0xFFFFFFFFu - idx);
}
// packed 2xFP32 FMA (Blackwell f32x2)
__device__ __forceinline__ void fma2(unsigned long long& acc, unsigned long long a, unsigned long long b){
    asm("fma.rn.f32x2 %0, %1, %2, %0;" : "+l"(acc) : "l"(a), "l"(b));
}
__device__ __forceinline__ unsigned long long splat2(float x){
    unsigned long long r;
    asm("mov.b64 %0, {%1, %1};" : "=l"(r) : "r"(__float_as_uint(x)));
    return r;
}
__device__ __forceinline__ void unpack2(unsigned long long v, float& lo, float& hi){
    unsigned a,b;
    asm("mov.b64 {%0, %1}, %2;" : "=r"(a), "=r"(b) : "l"(v));
    lo=__uint_as_float(a); hi=__uint_as_float(b);
}
__device__ __forceinline__ float hsum2(unsigned long long v){
    float lo,hi; unpack2(v,lo,hi); return lo+hi;
}

// ---------------- K0: prep = init + all normalizations ----------------
__global__ void __launch_bounds__(256) k_prep(const float* __restrict__ sup,
                                              const float* __restrict__ unl,
                                              const float* __restrict__ qx,
                                              float* __restrict__ out, int out_size){
    int s = blockIdx.x;
    int tid = threadIdx.x;
    if (s >= 800){
        int i = (s-800)*256 + tid;
        const int stride = 16*256;
        for (int t=i;t<BB*MU;t+=stride) g_rowbest[t]=0ULL;
        for (int t=i;t<BB*COLS;t+=stride) g_colbest[t]=0ULL;
        for (int t=i;t<BB*CC*(COLP-COLS);t+=stride){
            int bc=t/(COLP-COLS), p=t%(COLP-COLS);
            g_sup_t[(size_t)bc*COLP+COLS+p]=0.f;
        }
        for (int t=i;t<BB*CC*(MUP-MU);t+=stride){
            int bc=t/(MUP-MU), p=t%(MUP-MU);
            g_unl_t[(size_t)bc*MUP+MU+p]=0.f;
        }
        if (i==0) g_L[0]=0;
        for (int t=i;t<out_size;t+=stride) out[t]=0.f;
        return;
    }
    __shared__ float tile[1600];
    __shared__ float inv[HWN];
    const float* in;
    if (s<100)      in = sup + (size_t)s*1600;
    else if (s<500) in = unl + (size_t)(s-100)*1600;
    else            in = qx  + (size_t)(s-500)*1600;
    for (int t=tid;t<1600;t+=256) tile[t]=in[t];
    __syncthreads();
    if (tid<HWN){
        float a=0.f;
        for (int c=0;c<CC;++c){ float v=tile[c*HWN+tid]; a=fmaf(v,v,a); }
        inv[tid]=1.0f/fmaxf(sqrtf(a),1e-12f);
    }
    __syncthreads();
    if (s<100){
        int b=s/25, sk=s%25, w=sk/5, k=sk%5;
        int colbase=w*MS+k*25;
        float* outp=g_sup_n+(size_t)(b*COLS+colbase)*CC;
        float* outt=g_sup_t+(size_t)b*CC*COLP+colbase;
        for (int o=tid;o<1600;o+=256){ int hw=o>>6,c=o&63; outp[o]=tile[c*HWN+hw]*inv[hw]; }
        for (int o=tid;o<1600;o+=256){ int c=o/HWN,hw=o%HWN; outt[(size_t)c*COLP+hw]=tile[o]*inv[hw]; }
    } else if (s<500){
        int t2=s-100; int b=t2/100,u=t2%100;
        float* outp=g_unl_n+(size_t)(b*MU+u*25)*CC;
        float* outt=g_unl_t+(size_t)b*CC*MUP+u*25;
        for (int o=tid;o<1600;o+=256){ int hw=o>>6,c=o&63; outp[o]=tile[c*HWN+hw]*inv[hw]; }
        for (int o=tid;o<1600;o+=256){ int c=o/HWN,hw=o%HWN; outt[(size_t)c*MUP+hw]=tile[o]*inv[hw]; }
    } else {
        float* outp=g_q_n+(size_t)(s-500)*1600;
        for (int o=tid;o<1600;o+=256){ int hw=o>>6,c=o&63; outp[o]=tile[c*HWN+hw]*inv[hw]; }
    }
}

// ---------------- K1: u2s GEMM (f32x2) + packed row/col argmax ----------------
// block: 128 threads, 128 cols x 128 m tile, K=64 resident.
__global__ void __launch_bounds__(128,3) k_u2s(){
    __shared__ float4 s4[2048];                  // [c][32 f4] = 128 cols (32KB)
    __shared__ float4 u4[2048];                  // [c][32 f4] = 128 m   (32KB)
    __shared__ unsigned long long sm_col[128];   // per-tile-col best
    int mt=blockIdx.x, cp=blockIdx.y, b=blockIdx.z;
    int tid=threadIdx.x, lane=tid&31;
    int ci=tid&7, mi=tid>>3;

    const float4* gs4=(const float4*)g_sup_t + (size_t)b*(CC*COLP/4) + cp*32;
    #pragma unroll
    for (int t=0;t<16;++t){
        int idx=tid+t*128; int c=idx>>5, x=idx&31;
        s4[idx]=gs4[(size_t)c*(COLP/4)+x];
    }
    const float4* gu4=(const float4*)g_unl_t + (size_t)b*(CC*MUP/4) + mt*32;
    #pragma unroll
    for (int t=0;t<16;++t){
        int idx=tid+t*128; int c=idx>>5, x=idx&31;
        u4[idx]=gu4[(size_t)c*(MUP/4)+x];
    }
    sm_col[tid]=0ULL;
    __syncthreads();

    unsigned long long rk[8];     // per-owned-m best over all 128 cols
    #pragma unroll
    for (int sdx=0;sdx<8;++sdx) rk[sdx]=0ULL;

    #pragma unroll 1
    for (int h=0; h<2; ++h){
        unsigned long long acc[8][4];
        #pragma unroll
        for (int j=0;j<8;++j)
            #pragma unroll
            for (int k2=0;k2<4;++k2) acc[j][k2]=0ULL;

        #pragma unroll 2
        for (int c=0;c<64;++c){
            float4 a0=s4[c*32+h*16+ci];      // cols h*64+ci*4 +0..3
            float4 a1=s4[c*32+h*16+8+ci];    // cols h*64+32+ci*4 +0..3
            ulonglong2 bb0=*(const ulonglong2*)&u4[c*32+mi];      // m mi*4 pairs
            ulonglong2 bb1=*(const ulonglong2*)&u4[c*32+16+mi];   // m 64+mi*4 pairs
            unsigned long long pb0=bb0.x, pb1=bb0.y, pb2=bb1.x, pb3=bb1.y;
            float av[8]={a0.x,a0.y,a0.z,a0.w,a1.x,a1.y,a1.z,a1.w};
            #pragma unroll
            for (int j=0;j<8;++j){
                unsigned long long sa=splat2(av[j]);
                fma2(acc[j][0],sa,pb0);
                fma2(acc[j][1],sa,pb1);
                fma2(acc[j][2],sa,pb2);
                fma2(acc[j][3],sa,pb3);
            }
        }
        // epilogue: build row (per-m) and col (per-col) packed keys
        #pragma unroll
        for (int j=0;j<8;++j){
            int colj = cp*128 + h*64 + ((j<4)? ci*4+j : 32+ci*4+(j-4));
            bool vc = colj < COLS;
            unsigned long long ck=0ULL;
            #pragma unroll
            for (int k2=0;k2<4;++k2){
                float lo,hi; unpack2(acc[j][k2],lo,hi);
                int mloc = (k2<2)? mi*4+2*k2 : 64+mi*4+2*(k2-2);
                int mglo = mt*128+mloc, mghi = mglo+1;
                if (vc){
                    unsigned long long kl=packkey(lo,(unsigned)colj);
                    unsigned long long kh=packkey(hi,(unsigned)colj);
                    if (kl>rk[2*k2])   rk[2*k2]=kl;
                    if (kh>rk[2*k2+1]) rk[2*k2+1]=kh;
                    if (mglo<MU){ unsigned long long c1=packkey(lo,(unsigned)mglo); if (c1>ck) ck=c1; }
                    if (mghi<MU){ unsigned long long c2=packkey(hi,(unsigned)mghi); if (c2>ck) ck=c2; }
                }
            }
            // reduce over mi within warp (ci preserved by xor 8,16)
            #pragma unroll
            for (int off=8;off<=16;off<<=1){
                unsigned long long o=__shfl_xor_sync(0xffffffffu,ck,off);
                if (o>ck) ck=o;
            }
            if (lane<8 && ck){
                int local = h*64 + ((j<4)? lane*4+j : 32+lane*4+(j-4));
                atomicMax(&sm_col[local], ck);
            }
        }
    }
    // row reduce over ci (xor 1,2,4 preserves mi group)
    #pragma unroll
    for (int sdx=0;sdx<8;++sdx){
        unsigned long long v=rk[sdx];
        #pragma unroll
        for (int off=1;off<=4;off<<=1){
            unsigned long long o=__shfl_xor_sync(0xffffffffu,v,off);
            if (o>v) v=o;
        }
        if ((lane&7)==0 && v){
            int mloc = (sdx<4)? mi*4+sdx : 64+mi*4+(sdx-4);
            int mg = mt*128+mloc;
            if (mg<MU) atomicMax(&g_rowbest[(size_t)b*MU+mg], v);
        }
    }
    __syncthreads();
    if ((cp*128+tid)<COLS && sm_col[tid])
        atomicMax(&g_colbest[(size_t)b*COLS+cp*128+tid], sm_col[tid]);
}

// ---------------- K2: umask + stable stream compaction + L ----------------
__global__ void k_compact(){
    int bw = blockIdx.x; int b = bw/NWAY, w = bw%NWAY;
    int tid = threadIdx.x, lane = tid&31, wid = tid>>5;
    __shared__ int wsum[8], woff[8], sbase;
    if (tid==0) sbase=0;
    __syncthreads();
    for (int chunk=0; chunk<10; ++chunk){
        int m = chunk*256 + tid;
        bool flag = false;
        if (m < MU){
            unsigned long long rb = g_rowbest[b*MU+m];
            unsigned col = 0xFFFFFFFFu - (unsigned)(rb & 0xFFFFFFFFu);
            if ((int)(col/MS) == w){
                unsigned long long cb = g_colbest[b*COLS+col];
                unsigned mm = 0xFFFFFFFFu - (unsigned)(cb & 0xFFFFFFFFu);
                flag = (mm == (unsigned)m);
            }
        }
        unsigned bal = __ballot_sync(0xffffffffu, flag);
        if (lane==0) wsum[wid] = __popc(bal);
        __syncthreads();
        if (tid==0){
            int run=sbase;
            for (int i=0;i<8;++i){ woff[i]=run; run+=wsum[i]; }
            sbase=run;
        }
        __syncthreads();
        if (flag){
            int pos = woff[wid] + __popc(bal & ((1u<<lane)-1u));
            g_sel[(b*NWAY+w)*MU + pos] = m;
        }
        __syncthreads();
    }
    if (tid==0){
        g_count[b*NWAY+w] = sbase;
        atomicMax(&g_L[0], sbase);
    }
}

// ---------------- K3: fused query sim / mutual mask / CE loss -------------
template<int MQ0, int NMQ>
__device__ __forceinline__ void col_dot(const ulonglong2* __restrict__ qn2,
                                        const ulonglong2* __restrict__ vp2,
                                        float* __restrict__ vals){
    unsigned long long acc[NMQ];
    #pragma unroll
    for (int k=0;k<NMQ;++k) acc[k]=0ULL;
    #pragma unroll 4
    for (int c4=0;c4<16;++c4){
        ulonglong2 v=vp2[c4];
        #pragma unroll
        for (int k=0;k<NMQ;++k){
            ulonglong2 a=qn2[(MQ0+k)*16+c4];
            fma2(acc[k],a.x,v.x);
            fma2(acc[k],a.y,v.y);
        }
    }
    #pragma unroll
    for (int k=0;k<NMQ;++k) vals[MQ0+k]=hsum2(acc[k]);
}

__global__ void __launch_bounds__(256,2) k_sim(const int* __restrict__ qy,
                                               float* __restrict__ out){
    int q = blockIdx.x, b = blockIdx.y;
    int tid = threadIdx.x, lane = tid&31;
    __shared__ __align__(16) float qn_s[HWN*CC];     // [mq][c]
    __shared__ unsigned long long rowq[NWAY*HWN];    // packed per-(way,mq) best (raw cos)
    __shared__ unsigned char colmq[NWAY*MTOT];       // per-column argmax over mq
    __shared__ int cnt_s[NWAY];
    __shared__ int sL;

    if (tid < NWAY*HWN) rowq[tid]=0ULL;
    if (tid < NWAY) cnt_s[tid]=g_count[b*NWAY+tid];
    if (tid==0) sL = g_L[0];
    {
        const float4* src=(const float4*)(g_q_n+(size_t)(b*QQ+q)*1600);
        float4* dst=(float4*)qn_s;
        for (int t=tid;t<400;t+=256) dst[t]=src[t];
    }
    __syncthreads();
    const ulonglong2* qn2 = (const ulonglong2*)qn_s;

    for (int w=0; w<NWAY; ++w){
        int cw = cnt_s[w];
        int wl = MS + cw;
        unsigned long long wb[HWN];
        #pragma unroll
        for (int i=0;i<HWN;++i) wb[i]=0ULL;

        for (int j=tid; j<wl; j+=256){
            const float* vp = (j<MS) ? g_sup_n + (size_t)(b*COLS + w*MS + j)*CC
                                     : g_unl_n + (size_t)(b*MU + g_sel[(b*NWAY+w)*MU + (j-MS)])*CC;
            const ulonglong2* vp2 = (const ulonglong2*)vp;
            float vals[HWN];
            col_dot<0,13>(qn2, vp2, vals);
            col_dot<13,12>(qn2, vp2, vals);

            // raw cosine domain (monotone wrt (x+1)/2): argmaxes identical
            float best=-1e30f; int bmq=0;
            #pragma unroll
            for (int mq=0;mq<HWN;++mq){
                if (vals[mq]>best){best=vals[mq];bmq=mq;}
            }
            colmq[w*MTOT+j]=(unsigned char)bmq;
            unsigned gcol = (unsigned)(w*MTOT + j);
            #pragma unroll
            for (int mq=0;mq<HWN;++mq){
                unsigned long long k = packkey(vals[mq], gcol);
                if (k>wb[mq]) wb[mq]=k;
            }
        }
        #pragma unroll
        for (int mq=0;mq<HWN;++mq){
            unsigned long long v=wb[mq];
            #pragma unroll
            for (int off=16;off>=1;off>>=1){
                unsigned long long o=__shfl_xor_sync(0xffffffffu,v,off);
                if (o>v) v=o;
            }
            if (lane==0) atomicMax(&rowq[w*HWN+mq], v);
        }
    }
    __syncthreads();

    if (tid < 32){
        float rmx[NWAY]={0.f,0.f,0.f,0.f,0.f};
        unsigned long long qb=0ULL;
        float maskv=0.f;
        if (lane < HWN){
            #pragma unroll
            for (int w=0;w<NWAY;++w){
                unsigned long long r = rowq[w*HWN+lane];
                int cw=cnt_s[w];
                if (cw < sL){
                    // first all-zero pad column: raw cos = 0.0 exactly, colargmax mq=0
                    unsigned long long pk = packkey(0.0f,(unsigned)(w*MTOT+MS+cw));
                    if (pk>r) r=pk;
                }
                rmx[w]=fmaf(funmap((unsigned)(r>>32)),0.5f,0.5f);  // (cos+1)/2
                if (r>qb) qb=r;
            }
            unsigned gcol = 0xFFFFFFFFu - (unsigned)(qb & 0xFFFFFFFFu);
            int w_ = (int)(gcol / MTOT), j_ = (int)(gcol % MTOT);
            int amq = (j_ < MS + cnt_s[w_]) ? (int)colmq[w_*MTOT+j_] : 0;
            maskv = (amq==lane) ? 1.f : 0.f;
        }
        float qv[NWAY];
        #pragma unroll
        for (int w=0;w<NWAY;++w){
            float t = (lane<HWN) ? rmx[w]*maskv : 0.f;
            #pragma unroll
            for (int off=16;off>=1;off>>=1) t += __shfl_xor_sync(0xffffffffu,t,off);
            qv[w]=t;
        }
        if (lane==0){
            int y = qy[b*QQ+q];
            float mx=qv[0];
            #pragma unroll
            for (int w=1;w<NWAY;++w) mx=fmaxf(mx,qv[w]);
            float se=0.f;
            #pragma unroll
            for (int w=0;w<NWAY;++w) se += expf(qv[w]-mx);
            float li = mx + logf(se) - qv[y];
            atomicAdd(out, li*(1.0f/(float)(BB*QQ)));
        }
    }
}

// ---------------- launch ----------------
extern "C" void kernel_launch(void* const* d_in, const int* in_sizes, int n_in,
                              void* d_out, int out_size) {
    const float* sup = nullptr;
    const float* qx  = nullptr;
    const float* ux  = nullptr;
    const int*   qy  = nullptr;
    for (int i=0;i<n_in;++i){
        switch (in_sizes[i]){
            case 160000: sup = (const float*)d_in[i]; break; // support_xf
            case 480000: qx  = (const float*)d_in[i]; break; // query_xf
            case 640000: ux  = (const float*)d_in[i]; break; // unlabeled_xf
            case 300:    qy  = (const int*)d_in[i];   break; // query_y
            default: break;                                  // support_y unused
        }
    }
    float* out = (float*)d_out;
    k_prep<<<816,256>>>(sup, ux, qx, out, out_size);
    k_u2s<<<dim3(20,5,BB),128>>>();
    k_compact<<<BB*NWAY,256>>>();
    k_sim<<<dim3(QQ,BB),256>>>(qy, out);
}

// round 4
// speedup vs baseline: 2.4385x; 1.1934x over previous
#include <cuda_runtime.h>
#include <math.h>

#define NWAY 5
#define BB 4
#define CC 64
#define HWN 25
#define MS 125      // K_SHOT * h * w
#define MU 2500     // u * h * w
#define QQ 75
#define COLS 625    // NWAY * MS
#define MTOT 2625   // MS + MU
#define COLP 640    // padded cols for transposed support
#define MUP 2560    // padded m for transposed unlabeled
#define QROWS 2400  // 75 q * 32 padded rows
#define QROWP 2432  // padded to 19*128
#define CATP 2688   // padded cat columns (21*128)

// ---------------- scratch (static device allocations only) ----------------
__device__ float g_sup_t[BB*CC*COLP];            // [b][c][col] transposed support (pad zeroed)
__device__ float g_unl_t[BB*CC*MUP];             // [b][c][m]   transposed unlabeled (pad zeroed)
__device__ float g_q_t[BB*CC*QROWP];             // [b][c][q*32+mq] transposed query (pads zero)
__device__ float g_cat_t[BB*NWAY*CC*CATP];       // [bw][c][j] = [sup(125) | compacted unl(cw)]
__device__ unsigned long long g_rowbest[BB*MU];  // per (b,m): packed (val,col) argmax
__device__ unsigned long long g_colbest[BB*COLS];// per (b,col): packed (val,m) argmax
__device__ unsigned long long g_rowq[BB*QROWP*NWAY]; // per (b,row,w): packed best over cols
__device__ unsigned char g_colmq[(size_t)BB*QQ*NWAY*MTOT]; // per (b,q,w,j): argmax mq
__device__ int g_sel[BB*NWAY*MU];                // compacted m-indices per (b,way)
__device__ int g_count[BB*NWAY];
__device__ int g_L[1];

// monotone float ordering map (handles negatives exactly)
__device__ __forceinline__ unsigned fmap(float f){
    unsigned b=__float_as_uint(f);
    return (b&0x80000000u)? ~b : (b|0x80000000u);
}
__device__ __forceinline__ float funmap(unsigned u){
    return (u&0x80000000u)? __uint_as_float(u^0x80000000u) : __uint_as_float(~u);
}
// max-value, min-index-on-tie key (matches jnp first-occurrence argmax)
__device__ __forceinline__ unsigned long long packkey(float v, unsigned idx){
    return (((unsigned long long)fmap(v))<<32) | (unsigned long long)(0xFFFFFFFFu - idx);
}
// packed 2xFP32 FMA (Blackwell f32x2)
__device__ __forceinline__ void fma2(unsigned long long& acc, unsigned long long a, unsigned long long b){
    asm("fma.rn.f32x2 %0, %1, %2, %0;" : "+l"(acc) : "l"(a), "l"(b));
}
__device__ __forceinline__ unsigned long long splat2(float x){
    unsigned long long r;
    asm("mov.b64 %0, {%1, %1};" : "=l"(r) : "r"(__float_as_uint(x)));
    return r;
}
__device__ __forceinline__ void unpack2(unsigned long long v, float& lo, float& hi){
    unsigned a,b;
    asm("mov.b64 {%0, %1}, %2;" : "=r"(a), "=r"(b) : "l"(v));
    lo=__uint_as_float(a); hi=__uint_as_float(b);
}

// ---------------- K0: prep = init + all normalizations ----------------
__global__ void __launch_bounds__(256) k_prep(const float* __restrict__ sup,
                                              const float* __restrict__ unl,
                                              const float* __restrict__ qx,
                                              float* __restrict__ out, int out_size){
    int s = blockIdx.x;
    int tid = threadIdx.x;
    if (s >= 800){
        int i = (s-800)*256 + tid;
        const int stride = 16*256;
        for (int t=i;t<BB*MU;t+=stride) g_rowbest[t]=0ULL;
        for (int t=i;t<BB*COLS;t+=stride) g_colbest[t]=0ULL;
        for (int t=i;t<BB*QROWP*NWAY;t+=stride) g_rowq[t]=0ULL;
        for (int t=i;t<BB*CC*(COLP-COLS);t+=stride){
            int bc=t/(COLP-COLS), p=t%(COLP-COLS);
            g_sup_t[(size_t)bc*COLP+COLS+p]=0.f;
        }
        for (int t=i;t<BB*CC*(MUP-MU);t+=stride){
            int bc=t/(MUP-MU), p=t%(MUP-MU);
            g_unl_t[(size_t)bc*MUP+MU+p]=0.f;
        }
        // pad rows 2400..2431 of g_q_t
        for (int t=i;t<BB*CC*(QROWP-QROWS);t+=stride){
            int bc=t/(QROWP-QROWS), p=t%(QROWP-QROWS);
            g_q_t[(size_t)bc*QROWP+QROWS+p]=0.f;
        }
        if (i==0) g_L[0]=0;
        for (int t=i;t<out_size;t+=stride) out[t]=0.f;
        return;
    }
    __shared__ float tile[1600];
    __shared__ float inv[HWN];
    const float* in;
    if (s<100)      in = sup + (size_t)s*1600;
    else if (s<500) in = unl + (size_t)(s-100)*1600;
    else            in = qx  + (size_t)(s-500)*1600;
    for (int t=tid;t<1600;t+=256) tile[t]=in[t];
    __syncthreads();
    if (tid<HWN){
        float a=0.f;
        for (int c=0;c<CC;++c){ float v=tile[c*HWN+tid]; a=fmaf(v,v,a); }
        inv[tid]=1.0f/fmaxf(sqrtf(a),1e-12f);
    }
    __syncthreads();
    if (s<100){
        int b=s/25, sk=s%25, w=sk/5, k=sk%5;
        int colbase=w*MS+k*25;
        float* outt=g_sup_t+(size_t)b*CC*COLP+colbase;
        for (int o=tid;o<1600;o+=256){ int c=o/HWN,hw=o%HWN; outt[(size_t)c*COLP+hw]=tile[o]*inv[hw]; }
    } else if (s<500){
        int t2=s-100; int b=t2/100,u=t2%100;
        float* outt=g_unl_t+(size_t)b*CC*MUP+u*25;
        for (int o=tid;o<1600;o+=256){ int c=o/HWN,hw=o%HWN; outt[(size_t)c*MUP+hw]=tile[o]*inv[hw]; }
    } else {
        int t2=s-500; int b=t2/QQ, q=t2%QQ;
        float* outt=g_q_t+(size_t)b*CC*QROWP + q*32;
        for (int o=tid;o<1600;o+=256){ int c=o/HWN,hw=o%HWN; outt[(size_t)c*QROWP+hw]=tile[o]*inv[hw]; }
        for (int o=tid;o<CC*7;o+=256){ int c=o/7, mq=25+o%7; outt[(size_t)c*QROWP+mq]=0.f; }
    }
}

// ---------------- K1: u2s GEMM (f32x2) + packed row/col argmax ----------------
__global__ void __launch_bounds__(128,3) k_u2s(){
    __shared__ float4 s4[2048];                  // [c][32 f4] = 128 cols (32KB)
    __shared__ float4 u4[2048];                  // [c][32 f4] = 128 m   (32KB)
    __shared__ unsigned long long sm_col[128];
    int mt=blockIdx.x, cp=blockIdx.y, b=blockIdx.z;
    int tid=threadIdx.x, lane=tid&31;
    int ci=tid&7, mi=tid>>3;

    const float4* gs4=(const float4*)g_sup_t + (size_t)b*(CC*COLP/4) + cp*32;
    #pragma unroll
    for (int t=0;t<16;++t){
        int idx=tid+t*128; int c=idx>>5, x=idx&31;
        s4[idx]=gs4[(size_t)c*(COLP/4)+x];
    }
    const float4* gu4=(const float4*)g_unl_t + (size_t)b*(CC*MUP/4) + mt*32;
    #pragma unroll
    for (int t=0;t<16;++t){
        int idx=tid+t*128; int c=idx>>5, x=idx&31;
        u4[idx]=gu4[(size_t)c*(MUP/4)+x];
    }
    sm_col[tid]=0ULL;
    __syncthreads();

    unsigned long long rk[8];
    #pragma unroll
    for (int sdx=0;sdx<8;++sdx) rk[sdx]=0ULL;

    #pragma unroll 1
    for (int h=0; h<2; ++h){
        unsigned long long acc[8][4];
        #pragma unroll
        for (int j=0;j<8;++j)
            #pragma unroll
            for (int k2=0;k2<4;++k2) acc[j][k2]=0ULL;

        #pragma unroll 2
        for (int c=0;c<64;++c){
            float4 a0=s4[c*32+h*16+ci];
            float4 a1=s4[c*32+h*16+8+ci];
            ulonglong2 bb0=*(const ulonglong2*)&u4[c*32+mi];
            ulonglong2 bb1=*(const ulonglong2*)&u4[c*32+16+mi];
            unsigned long long pb0=bb0.x, pb1=bb0.y, pb2=bb1.x, pb3=bb1.y;
            float av[8]={a0.x,a0.y,a0.z,a0.w,a1.x,a1.y,a1.z,a1.w};
            #pragma unroll
            for (int j=0;j<8;++j){
                unsigned long long sa=splat2(av[j]);
                fma2(acc[j][0],sa,pb0);
                fma2(acc[j][1],sa,pb1);
                fma2(acc[j][2],sa,pb2);
                fma2(acc[j][3],sa,pb3);
            }
        }
        #pragma unroll
        for (int j=0;j<8;++j){
            int colj = cp*128 + h*64 + ((j<4)? ci*4+j : 32+ci*4+(j-4));
            bool vc = colj < COLS;
            unsigned long long ck=0ULL;
            #pragma unroll
            for (int k2=0;k2<4;++k2){
                float lo,hi; unpack2(acc[j][k2],lo,hi);
                int mloc = (k2<2)? mi*4+2*k2 : 64+mi*4+2*(k2-2);
                int mglo = mt*128+mloc, mghi = mglo+1;
                if (vc){
                    unsigned long long kl=packkey(lo,(unsigned)colj);
                    unsigned long long kh=packkey(hi,(unsigned)colj);
                    if (kl>rk[2*k2])   rk[2*k2]=kl;
                    if (kh>rk[2*k2+1]) rk[2*k2+1]=kh;
                    if (mglo<MU){ unsigned long long c1=packkey(lo,(unsigned)mglo); if (c1>ck) ck=c1; }
                    if (mghi<MU){ unsigned long long c2=packkey(hi,(unsigned)mghi); if (c2>ck) ck=c2; }
                }
            }
            #pragma unroll
            for (int off=8;off<=16;off<<=1){
                unsigned long long o=__shfl_xor_sync(0xffffffffu,ck,off);
                if (o>ck) ck=o;
            }
            if (lane<8 && ck){
                int local = h*64 + ((j<4)? lane*4+j : 32+lane*4+(j-4));
                atomicMax(&sm_col[local], ck);
            }
        }
    }
    #pragma unroll
    for (int sdx=0;sdx<8;++sdx){
        unsigned long long v=rk[sdx];
        #pragma unroll
        for (int off=1;off<=4;off<<=1){
            unsigned long long o=__shfl_xor_sync(0xffffffffu,v,off);
            if (o>v) v=o;
        }
        if ((lane&7)==0 && v){
            int mloc = (sdx<4)? mi*4+sdx : 64+mi*4+(sdx-4);
            int mg = mt*128+mloc;
            if (mg<MU) atomicMax(&g_rowbest[(size_t)b*MU+mg], v);
        }
    }
    __syncthreads();
    if ((cp*128+tid)<COLS && sm_col[tid])
        atomicMax(&g_colbest[(size_t)b*COLS+cp*128+tid], sm_col[tid]);
}

// ---------------- K2: umask + stable stream compaction + L ----------------
__global__ void k_compact(){
    int bw = blockIdx.x; int b = bw/NWAY, w = bw%NWAY;
    int tid = threadIdx.x, lane = tid&31, wid = tid>>5;
    __shared__ int wsum[8], woff[8], sbase;
    if (tid==0) sbase=0;
    __syncthreads();
    for (int chunk=0; chunk<10; ++chunk){
        int m = chunk*256 + tid;
        bool flag = false;
        if (m < MU){
            unsigned long long rb = g_rowbest[b*MU+m];
            unsigned col = 0xFFFFFFFFu - (unsigned)(rb & 0xFFFFFFFFu);
            if ((int)(col/MS) == w){
                unsigned long long cb = g_colbest[b*COLS+col];
                unsigned mm = 0xFFFFFFFFu - (unsigned)(cb & 0xFFFFFFFFu);
                flag = (mm == (unsigned)m);
            }
        }
        unsigned bal = __ballot_sync(0xffffffffu, flag);
        if (lane==0) wsum[wid] = __popc(bal);
        __syncthreads();
        if (tid==0){
            int run=sbase;
            for (int i=0;i<8;++i){ woff[i]=run; run+=wsum[i]; }
            sbase=run;
        }
        __syncthreads();
        if (flag){
            int pos = woff[wid] + __popc(bal & ((1u<<lane)-1u));
            g_sel[(b*NWAY+w)*MU + pos] = m;
        }
        __syncthreads();
    }
    if (tid==0){
        g_count[b*NWAY+w] = sbase;
        atomicMax(&g_L[0], sbase);
    }
}

// ---------------- K3: gather concatenated transposed columns per (b,w) ------
__global__ void __launch_bounds__(256) k_gather(){
    int bw = blockIdx.x; int b = bw/NWAY, w = bw%NWAY;
    int c0 = blockIdx.y*16;
    int tid = threadIdx.x;
    __shared__ int sel_s[MU];
    int cw = g_count[bw];
    for (int j=tid;j<cw;j+=256) sel_s[j]=g_sel[bw*MU+j];
    __syncthreads();
    for (int c=c0;c<c0+16;++c){
        float* dst = g_cat_t + ((size_t)bw*CC+c)*CATP;
        const float* ssrc = g_sup_t + ((size_t)b*CC+c)*COLP + w*MS;
        const float* usrc = g_unl_t + ((size_t)b*CC+c)*MUP;
        for (int j=tid;j<MS;j+=256) dst[j]=ssrc[j];
        for (int j=tid;j<cw;j+=256) dst[MS+j]=usrc[sel_s[j]];
    }
}

// ---------------- K4: query GEMM (f32x2) + row/colmq epilogue ----------------
__global__ void __launch_bounds__(128,3) k_qsim(){
    int ct=blockIdx.x, qt=blockIdx.y, bw=blockIdx.z;
    int b=bw/NWAY, w=bw%NWAY;
    int cw=g_count[bw]; int wl=MS+cw;
    if (ct*128 >= wl) return;
    __shared__ float4 a4[2048];                 // q-rows: [c][32 f4] = 128 rows (32KB)
    __shared__ float4 v4[2048];                 // cols:   [c][32 f4] = 128 cols (32KB)
    __shared__ unsigned long long smq[512];     // [group 0..3][128 cols]
    int tid=threadIdx.x, lane=tid&31, warp=tid>>5;
    int ci=tid&7, mi=tid>>3;

    const float4* ga=(const float4*)g_q_t + (size_t)b*(CC*QROWP/4) + qt*32;
    #pragma unroll
    for (int t=0;t<16;++t){
        int idx=tid+t*128; int c=idx>>5, x=idx&31;
        a4[idx]=ga[(size_t)c*(QROWP/4)+x];
    }
    const float4* gv=(const float4*)g_cat_t + (size_t)bw*(CC*CATP/4) + ct*32;
    #pragma unroll
    for (int t=0;t<16;++t){
        int idx=tid+t*128; int c=idx>>5, x=idx&31;
        v4[idx]=gv[(size_t)c*(CATP/4)+x];
    }
    #pragma unroll
    for (int t=0;t<4;++t) smq[tid+t*128]=0ULL;
    __syncthreads();

    unsigned long long rk[8];
    #pragma unroll
    for (int sdx=0;sdx<8;++sdx) rk[sdx]=0ULL;

    int gA = warp>>1;        // q-group for k2<2 accs
    #pragma unroll 1
    for (int h=0; h<2; ++h){
        unsigned long long acc[8][4];
        #pragma unroll
        for (int j=0;j<8;++j)
            #pragma unroll
            for (int k2=0;k2<4;++k2) acc[j][k2]=0ULL;

        #pragma unroll 2
        for (int c=0;c<64;++c){
            float4 a0=v4[c*32+h*16+ci];
            float4 a1=v4[c*32+h*16+8+ci];
            ulonglong2 bb0=*(const ulonglong2*)&a4[c*32+mi];
            ulonglong2 bb1=*(const ulonglong2*)&a4[c*32+16+mi];
            unsigned long long pb0=bb0.x, pb1=bb0.y, pb2=bb1.x, pb3=bb1.y;
            float av[8]={a0.x,a0.y,a0.z,a0.w,a1.x,a1.y,a1.z,a1.w};
            #pragma unroll
            for (int j=0;j<8;++j){
                unsigned long long sa=splat2(av[j]);
                fma2(acc[j][0],sa,pb0);
                fma2(acc[j][1],sa,pb1);
                fma2(acc[j][2],sa,pb2);
                fma2(acc[j][3],sa,pb3);
            }
        }
        #pragma unroll
        for (int j=0;j<8;++j){
            int coll = h*64 + ((j<4)? ci*4+j : 32+ci*4+(j-4));
            int jg = ct*128 + coll;
            bool vc = jg < wl;
            unsigned gcol = (unsigned)(w*MTOT + jg);
            unsigned long long keyA=0ULL, keyB=0ULL;
            #pragma unroll
            for (int k2=0;k2<4;++k2){
                float lo,hi; unpack2(acc[j][k2],lo,hi);
                int mloc = (k2<2)? mi*4+2*k2 : 64+mi*4+2*(k2-2);
                int mq = mloc & 31;
                int r = qt*128 + mloc;
                if (vc){
                    unsigned long long kl=packkey(lo,gcol);
                    unsigned long long kh=packkey(hi,gcol);
                    if (kl>rk[2*k2])   rk[2*k2]=kl;
                    if (kh>rk[2*k2+1]) rk[2*k2+1]=kh;
                    if (r < QROWS){
                        if (mq < HWN){
                            unsigned long long kq=packkey(lo,(unsigned)mq);
                            if (k2<2){ if (kq>keyA) keyA=kq; } else { if (kq>keyB) keyB=kq; }
                        }
                        if (mq+1 < HWN){
                            unsigned long long kq=packkey(hi,(unsigned)(mq+1));
                            if (k2<2){ if (kq>keyA) keyA=kq; } else { if (kq>keyB) keyB=kq; }
                        }
                    }
                }
            }
            #pragma unroll
            for (int off=8;off<=16;off<<=1){
                unsigned long long oA=__shfl_xor_sync(0xffffffffu,keyA,off);
                unsigned long long oB=__shfl_xor_sync(0xffffffffu,keyB,off);
                if (oA>keyA) keyA=oA;
                if (oB>keyB) keyB=oB;
            }
            if (lane<8){
                if (keyA) atomicMax(&smq[gA*128 + coll], keyA);
                if (keyB) atomicMax(&smq[(2+gA)*128 + coll], keyB);
            }
        }
    }
    #pragma unroll
    for (int sdx=0;sdx<8;++sdx){
        unsigned long long v=rk[sdx];
        #pragma unroll
        for (int off=1;off<=4;off<<=1){
            unsigned long long o=__shfl_xor_sync(0xffffffffu,v,off);
            if (o>v) v=o;
        }
        if ((lane&7)==0 && v){
            int mloc = (sdx<4)? mi*4+sdx : 64+mi*4+(sdx-4);
            int r = qt*128+mloc;
            int mq = mloc & 31;
            if (r<QROWS && mq<HWN)
                atomicMax(&g_rowq[((size_t)b*QROWP + r)*NWAY + w], v);
        }
    }
    __syncthreads();
    int jg = ct*128 + tid;
    if (jg < wl){
        #pragma unroll
        for (int g=0; g<4; ++g){
            int q = qt*4 + g;
            if (q < QQ){
                unsigned long long k = smq[g*128+tid];
                unsigned mq = 0xFFFFFFFFu - (unsigned)(k & 0xFFFFFFFFu);
                g_colmq[(((size_t)b*QQ+q)*NWAY+w)*MTOT + jg] = (unsigned char)mq;
            }
        }
    }
}

// ---------------- K5: finish = mutual mask + CE loss per (b,q) ----------------
__global__ void k_fin(const int* __restrict__ qy, float* __restrict__ out){
    int q=blockIdx.x, b=blockIdx.y;
    int lane=threadIdx.x;
    int sL=g_L[0];
    int cnt[NWAY];
    #pragma unroll
    for (int w=0;w<NWAY;++w) cnt[w]=g_count[b*NWAY+w];
    float rmx[NWAY]={0.f,0.f,0.f,0.f,0.f};
    unsigned long long qb=0ULL;
    float maskv=0.f;
    if (lane < HWN){
        #pragma unroll
        for (int w=0;w<NWAY;++w){
            unsigned long long r = g_rowq[((size_t)b*QROWP + q*32 + lane)*NWAY + w];
            if (cnt[w] < sL){
                unsigned long long pk = packkey(0.0f,(unsigned)(w*MTOT+MS+cnt[w]));
                if (pk>r) r=pk;
            }
            rmx[w]=fmaf(funmap((unsigned)(r>>32)),0.5f,0.5f);
            if (r>qb) qb=r;
        }
        unsigned gcol = 0xFFFFFFFFu - (unsigned)(qb & 0xFFFFFFFFu);
        int w_ = (int)(gcol / MTOT), j_ = (int)(gcol % MTOT);
        int amq = (j_ < MS+cnt[w_]) ? (int)g_colmq[(((size_t)b*QQ+q)*NWAY+w_)*MTOT + j_] : 0;
        maskv = (amq==lane) ? 1.f : 0.f;
    }
    float qv[NWAY];
    #pragma unroll
    for (int w=0;w<NWAY;++w){
        float t = (lane<HWN) ? rmx[w]*maskv : 0.f;
        #pragma unroll
        for (int off=16;off>=1;off>>=1) t += __shfl_xor_sync(0xffffffffu,t,off);
        qv[w]=t;
    }
    if (lane==0){
        int y = qy[b*QQ+q];
        float mx=qv[0];
        #pragma unroll
        for (int w=1;w<NWAY;++w) mx=fmaxf(mx,qv[w]);
        float se=0.f;
        #pragma unroll
        for (int w=0;w<NWAY;++w) se += expf(qv[w]-mx);
        float li = mx + logf(se) - qv[y];
        atomicAdd(out, li*(1.0f/(float)(BB*QQ)));
    }
}

// ---------------- launch ----------------
extern "C" void kernel_launch(void* const* d_in, const int* in_sizes, int n_in,
                              void* d_out, int out_size) {
    const float* sup = nullptr;
    const float* qx  = nullptr;
    const float* ux  = nullptr;
    const int*   qy  = nullptr;
    for (int i=0;i<n_in;++i){
        switch (in_sizes[i]){
            case 160000: sup = (const float*)d_in[i]; break; // support_xf
            case 480000: qx  = (const float*)d_in[i]; break; // query_xf
            case 640000: ux  = (const float*)d_in[i]; break; // unlabeled_xf
            case 300:    qy  = (const int*)d_in[i];   break; // query_y
            default: break;                                  // support_y unused
        }
    }
    float* out = (float*)d_out;
    k_prep<<<816,256>>>(sup, ux, qx, out, out_size);
    k_u2s<<<dim3(20,5,BB),128>>>();
    k_compact<<<BB*NWAY,256>>>();
    k_gather<<<dim3(BB*NWAY,4),256>>>();
    k_qsim<<<dim3(21,19,BB*NWAY),128>>>();
    k_fin<<<dim3(QQ,BB),32>>>(qy, out);
}

// round 5
// speedup vs baseline: 2.5828x; 1.0592x over previous
#include <cuda_runtime.h>
#include <math.h>

#define NWAY 5
#define BB 4
#define CC 64
#define HWN 25
#define MS 125      // K_SHOT * h * w
#define MU 2500     // u * h * w
#define QQ 75
#define COLS 625    // NWAY * MS
#define MTOT 2625   // MS + MU
#define COLP 640    // padded cols for transposed support
#define MUP 2560    // padded m for transposed unlabeled
#define QROWS 2400  // 75 q * 32 padded rows
#define QROWP 2432  // padded to 19*128
#define CATP 2688   // padded cat columns (21*128)

// ---------------- scratch (static device allocations only) ----------------
__device__ float g_sup_t[BB*CC*COLP];            // [b][c][col] transposed support (pad zeroed)
__device__ float g_unl_t[BB*CC*MUP];             // [b][c][m]   transposed unlabeled (pad zeroed)
__device__ float g_q_t[BB*CC*QROWP];             // [b][c][q*32+mq] transposed query (pads zero)
__device__ float g_cat_t[BB*NWAY*CC*CATP];       // [bw][c][j] = [sup(125) | compacted unl(cw)]
__device__ unsigned long long g_rowbest[BB*MU];  // per (b,m): packed (val,col) argmax
__device__ unsigned long long g_colbest[BB*COLS];// per (b,col): packed (val,m) argmax
__device__ unsigned long long g_rowq[BB*QROWP*NWAY]; // per (b,row,w): packed best over cols
__device__ unsigned char g_colmq[(size_t)BB*QQ*NWAY*MTOT]; // per (b,q,w,j): argmax mq
__device__ int g_sel[BB*NWAY*MU];                // compacted m-indices per (b,way)
__device__ int g_count[BB*NWAY];
__device__ int g_L[1];

// monotone float ordering map (handles negatives exactly)
__device__ __forceinline__ unsigned fmap(float f){
    unsigned b=__float_as_uint(f);
    return (b&0x80000000u)? ~b : (b|0x80000000u);
}
__device__ __forceinline__ float funmap(unsigned u){
    return (u&0x80000000u)? __uint_as_float(u^0x80000000u) : __uint_as_float(~u);
}
// max-value, min-index-on-tie key (matches jnp first-occurrence argmax)
__device__ __forceinline__ unsigned long long packkey(float v, unsigned idx){
    return (((unsigned long long)fmap(v))<<32) | (unsigned long long)(0xFFFFFFFFu - idx);
}
// packed 2xFP32 FMA (Blackwell f32x2)
__device__ __forceinline__ void fma2(unsigned long long& acc, unsigned long long a, unsigned long long b){
    asm("fma.rn.f32x2 %0, %1, %2, %0;" : "+l"(acc) : "l"(a), "l"(b));
}
__device__ __forceinline__ unsigned long long splat2(float x){
    unsigned long long r;
    asm("mov.b64 %0, {%1, %1};" : "=l"(r) : "r"(__float_as_uint(x)));
    return r;
}
__device__ __forceinline__ void unpack2(unsigned long long v, float& lo, float& hi){
    unsigned a,b;
    asm("mov.b64 {%0, %1}, %2;" : "=r"(a), "=r"(b) : "l"(v));
    lo=__uint_as_float(a); hi=__uint_as_float(b);
}

// ---------------- K0: prep = init + all normalizations ----------------
__global__ void __launch_bounds__(256) k_prep(const float* __restrict__ sup,
                                              const float* __restrict__ unl,
                                              const float* __restrict__ qx,
                                              float* __restrict__ out, int out_size){
    int s = blockIdx.x;
    int tid = threadIdx.x;
    if (s >= 800){
        int i = (s-800)*256 + tid;
        const int stride = 16*256;
        for (int t=i;t<BB*MU;t+=stride) g_rowbest[t]=0ULL;
        for (int t=i;t<BB*COLS;t+=stride) g_colbest[t]=0ULL;
        for (int t=i;t<BB*QROWP*NWAY;t+=stride) g_rowq[t]=0ULL;
        for (int t=i;t<BB*CC*(COLP-COLS);t+=stride){
            int bc=t/(COLP-COLS), p=t%(COLP-COLS);
            g_sup_t[(size_t)bc*COLP+COLS+p]=0.f;
        }
        for (int t=i;t<BB*CC*(MUP-MU);t+=stride){
            int bc=t/(MUP-MU), p=t%(MUP-MU);
            g_unl_t[(size_t)bc*MUP+MU+p]=0.f;
        }
        // pad rows 2400..2431 of g_q_t
        for (int t=i;t<BB*CC*(QROWP-QROWS);t+=stride){
            int bc=t/(QROWP-QROWS), p=t%(QROWP-QROWS);
            g_q_t[(size_t)bc*QROWP+QROWS+p]=0.f;
        }
        if (i==0) g_L[0]=0;
        for (int t=i;t<out_size;t+=stride) out[t]=0.f;
        return;
    }
    __shared__ float tile[1600];
    __shared__ float inv[HWN];
    const float* in;
    if (s<100)      in = sup + (size_t)s*1600;
    else if (s<500) in = unl + (size_t)(s-100)*1600;
    else            in = qx  + (size_t)(s-500)*1600;
    for (int t=tid;t<1600;t+=256) tile[t]=in[t];
    __syncthreads();
    if (tid<HWN){
        float a=0.f;
        for (int c=0;c<CC;++c){ float v=tile[c*HWN+tid]; a=fmaf(v,v,a); }
        inv[tid]=1.0f/fmaxf(sqrtf(a),1e-12f);
    }
    __syncthreads();
    if (s<100){
        int b=s/25, sk=s%25, w=sk/5, k=sk%5;
        int colbase=w*MS+k*25;
        float* outt=g_sup_t+(size_t)b*CC*COLP+colbase;
        for (int o=tid;o<1600;o+=256){ int c=o/HWN,hw=o%HWN; outt[(size_t)c*COLP+hw]=tile[o]*inv[hw]; }
    } else if (s<500){
        int t2=s-100; int b=t2/100,u=t2%100;
        float* outt=g_unl_t+(size_t)b*CC*MUP+u*25;
        for (int o=tid;o<1600;o+=256){ int c=o/HWN,hw=o%HWN; outt[(size_t)c*MUP+hw]=tile[o]*inv[hw]; }
    } else {
        int t2=s-500; int b=t2/QQ, q=t2%QQ;
        float* outt=g_q_t+(size_t)b*CC*QROWP + q*32;
        for (int o=tid;o<1600;o+=256){ int c=o/HWN,hw=o%HWN; outt[(size_t)c*QROWP+hw]=tile[o]*inv[hw]; }
        for (int o=tid;o<CC*7;o+=256){ int c=o/7, mq=25+o%7; outt[(size_t)c*QROWP+mq]=0.f; }
    }
}

// ---------------- K1: u2s GEMM (f32x2) + packed row/col argmax ----------------
__global__ void __launch_bounds__(128,3) k_u2s(){
    __shared__ float4 s4[2048];                  // [c][32 f4] = 128 cols (32KB)
    __shared__ float4 u4[2048];                  // [c][32 f4] = 128 m   (32KB)
    __shared__ unsigned long long sm_col[128];
    int mt=blockIdx.x, cp=blockIdx.y, b=blockIdx.z;
    int tid=threadIdx.x, lane=tid&31;
    int ci=tid&7, mi=tid>>3;

    const float4* gs4=(const float4*)g_sup_t + (size_t)b*(CC*COLP/4) + cp*32;
    #pragma unroll
    for (int t=0;t<16;++t){
        int idx=tid+t*128; int c=idx>>5, x=idx&31;
        s4[idx]=gs4[(size_t)c*(COLP/4)+x];
    }
    const float4* gu4=(const float4*)g_unl_t + (size_t)b*(CC*MUP/4) + mt*32;
    #pragma unroll
    for (int t=0;t<16;++t){
        int idx=tid+t*128; int c=idx>>5, x=idx&31;
        u4[idx]=gu4[(size_t)c*(MUP/4)+x];
    }
    sm_col[tid]=0ULL;
    __syncthreads();

    unsigned long long rk[8];
    #pragma unroll
    for (int sdx=0;sdx<8;++sdx) rk[sdx]=0ULL;

    #pragma unroll 1
    for (int h=0; h<2; ++h){
        unsigned long long acc[8][4];
        #pragma unroll
        for (int j=0;j<8;++j)
            #pragma unroll
            for (int k2=0;k2<4;++k2) acc[j][k2]=0ULL;

        #pragma unroll 2
        for (int c=0;c<64;++c){
            float4 a0=s4[c*32+h*16+ci];
            float4 a1=s4[c*32+h*16+8+ci];
            ulonglong2 bb0=*(const ulonglong2*)&u4[c*32+mi];
            ulonglong2 bb1=*(const ulonglong2*)&u4[c*32+16+mi];
            unsigned long long pb0=bb0.x, pb1=bb0.y, pb2=bb1.x, pb3=bb1.y;
            float av[8]={a0.x,a0.y,a0.z,a0.w,a1.x,a1.y,a1.z,a1.w};
            #pragma unroll
            for (int j=0;j<8;++j){
                unsigned long long sa=splat2(av[j]);
                fma2(acc[j][0],sa,pb0);
                fma2(acc[j][1],sa,pb1);
                fma2(acc[j][2],sa,pb2);
                fma2(acc[j][3],sa,pb3);
            }
        }
        #pragma unroll
        for (int j=0;j<8;++j){
            int colj = cp*128 + h*64 + ((j<4)? ci*4+j : 32+ci*4+(j-4));
            bool vc = colj < COLS;
            unsigned long long ck=0ULL;
            #pragma unroll
            for (int k2=0;k2<4;++k2){
                float lo,hi; unpack2(acc[j][k2],lo,hi);
                int mloc = (k2<2)? mi*4+2*k2 : 64+mi*4+2*(k2-2);
                int mglo = mt*128+mloc, mghi = mglo+1;
                if (vc){
                    unsigned long long kl=packkey(lo,(unsigned)colj);
                    unsigned long long kh=packkey(hi,(unsigned)colj);
                    if (kl>rk[2*k2])   rk[2*k2]=kl;
                    if (kh>rk[2*k2+1]) rk[2*k2+1]=kh;
                    if (mglo<MU){ unsigned long long c1=packkey(lo,(unsigned)mglo); if (c1>ck) ck=c1; }
                    if (mghi<MU){ unsigned long long c2=packkey(hi,(unsigned)mghi); if (c2>ck) ck=c2; }
                }
            }
            #pragma unroll
            for (int off=8;off<=16;off<<=1){
                unsigned long long o=__shfl_xor_sync(0xffffffffu,ck,off);
                if (o>ck) ck=o;
            }
            if (lane<8 && ck){
                int local = h*64 + ((j<4)? lane*4+j : 32+lane*4+(j-4));
                atomicMax(&sm_col[local], ck);
            }
        }
    }
    #pragma unroll
    for (int sdx=0;sdx<8;++sdx){
        unsigned long long v=rk[sdx];
        #pragma unroll
        for (int off=1;off<=4;off<<=1){
            unsigned long long o=__shfl_xor_sync(0xffffffffu,v,off);
            if (o>v) v=o;
        }
        if ((lane&7)==0 && v){
            int mloc = (sdx<4)? mi*4+sdx : 64+mi*4+(sdx-4);
            int mg = mt*128+mloc;
            if (mg<MU) atomicMax(&g_rowbest[(size_t)b*MU+mg], v);
        }
    }
    __syncthreads();
    if ((cp*128+tid)<COLS && sm_col[tid])
        atomicMax(&g_colbest[(size_t)b*COLS+cp*128+tid], sm_col[tid]);
}

// ---------------- K2: umask + stable stream compaction + L ----------------
__global__ void k_compact(){
    int bw = blockIdx.x; int b = bw/NWAY, w = bw%NWAY;
    int tid = threadIdx.x, lane = tid&31, wid = tid>>5;
    __shared__ int wsum[8], woff[8], sbase;
    if (tid==0) sbase=0;
    __syncthreads();
    for (int chunk=0; chunk<10; ++chunk){
        int m = chunk*256 + tid;
        bool flag = false;
        if (m < MU){
            unsigned long long rb = g_rowbest[b*MU+m];
            unsigned col = 0xFFFFFFFFu - (unsigned)(rb & 0xFFFFFFFFu);
            if ((int)(col/MS) == w){
                unsigned long long cb = g_colbest[b*COLS+col];
                unsigned mm = 0xFFFFFFFFu - (unsigned)(cb & 0xFFFFFFFFu);
                flag = (mm == (unsigned)m);
            }
        }
        unsigned bal = __ballot_sync(0xffffffffu, flag);
        if (lane==0) wsum[wid] = __popc(bal);
        __syncthreads();
        if (tid==0){
            int run=sbase;
            for (int i=0;i<8;++i){ woff[i]=run; run+=wsum[i]; }
            sbase=run;
        }
        __syncthreads();
        if (flag){
            int pos = woff[wid] + __popc(bal & ((1u<<lane)-1u));
            g_sel[(b*NWAY+w)*MU + pos] = m;
        }
        __syncthreads();
    }
    if (tid==0){
        g_count[b*NWAY+w] = sbase;
        atomicMax(&g_L[0], sbase);
    }
}

// ---------------- K3: gather concatenated transposed columns per (bw, c) ----
// One block per (bw, channel): fully parallel, no smem staging, L2-resident gather.
__global__ void __launch_bounds__(256) k_gather(){
    int bw = blockIdx.x; int c = blockIdx.y;
    int b = bw/NWAY, w = bw%NWAY;
    int cw = g_count[bw];
    const int* __restrict__ sel = g_sel + (size_t)bw*MU;
    float* __restrict__ dst = g_cat_t + ((size_t)bw*CC+c)*CATP;
    const float* __restrict__ ssrc = g_sup_t + ((size_t)b*CC+c)*COLP + w*MS;
    const float* __restrict__ usrc = g_unl_t + ((size_t)b*CC+c)*MUP;
    int tid = threadIdx.x;
    for (int j=tid;j<MS;j+=256) dst[j]=ssrc[j];
    for (int j=tid;j<cw;j+=256) dst[MS+j]=usrc[__ldg(&sel[j])];
}

// ---------------- K4: query GEMM (f32x2) + row/colmq epilogue ----------------
__global__ void __launch_bounds__(128,3) k_qsim(){
    int ct=blockIdx.x, qt=blockIdx.y, bw=blockIdx.z;
    int b=bw/NWAY, w=bw%NWAY;
    int cw=g_count[bw]; int wl=MS+cw;
    if (ct*128 >= wl) return;
    __shared__ float4 a4[2048];                 // q-rows: [c][32 f4] = 128 rows (32KB)
    __shared__ float4 v4[2048];                 // cols:   [c][32 f4] = 128 cols (32KB)
    __shared__ unsigned long long smq[512];     // [group 0..3][128 cols]
    int tid=threadIdx.x, lane=tid&31, warp=tid>>5;
    int ci=tid&7, mi=tid>>3;

    const float4* ga=(const float4*)g_q_t + (size_t)b*(CC*QROWP/4) + qt*32;
    #pragma unroll
    for (int t=0;t<16;++t){
        int idx=tid+t*128; int c=idx>>5, x=idx&31;
        a4[idx]=ga[(size_t)c*(QROWP/4)+x];
    }
    const float4* gv=(const float4*)g_cat_t + (size_t)bw*(CC*CATP/4) + ct*32;
    #pragma unroll
    for (int t=0;t<16;++t){
        int idx=tid+t*128; int c=idx>>5, x=idx&31;
        v4[idx]=gv[(size_t)c*(CATP/4)+x];
    }
    #pragma unroll
    for (int t=0;t<4;++t) smq[tid+t*128]=0ULL;
    __syncthreads();

    unsigned long long rk[8];
    #pragma unroll
    for (int sdx=0;sdx<8;++sdx) rk[sdx]=0ULL;

    int gA = warp>>1;        // q-group for k2<2 accs
    #pragma unroll 1
    for (int h=0; h<2; ++h){
        unsigned long long acc[8][4];
        #pragma unroll
        for (int j=0;j<8;++j)
            #pragma unroll
            for (int k2=0;k2<4;++k2) acc[j][k2]=0ULL;

        #pragma unroll 2
        for (int c=0;c<64;++c){
            float4 a0=v4[c*32+h*16+ci];
            float4 a1=v4[c*32+h*16+8+ci];
            ulonglong2 bb0=*(const ulonglong2*)&a4[c*32+mi];
            ulonglong2 bb1=*(const ulonglong2*)&a4[c*32+16+mi];
            unsigned long long pb0=bb0.x, pb1=bb0.y, pb2=bb1.x, pb3=bb1.y;
            float av[8]={a0.x,a0.y,a0.z,a0.w,a1.x,a1.y,a1.z,a1.w};
            #pragma unroll
            for (int j=0;j<8;++j){
                unsigned long long sa=splat2(av[j]);
                fma2(acc[j][0],sa,pb0);
                fma2(acc[j][1],sa,pb1);
                fma2(acc[j][2],sa,pb2);
                fma2(acc[j][3],sa,pb3);
            }
        }
        #pragma unroll
        for (int j=0;j<8;++j){
            int coll = h*64 + ((j<4)? ci*4+j : 32+ci*4+(j-4));
            int jg = ct*128 + coll;
            bool vc = jg < wl;
            unsigned gcol = (unsigned)(w*MTOT + jg);
            unsigned long long keyA=0ULL, keyB=0ULL;
            #pragma unroll
            for (int k2=0;k2<4;++k2){
                float lo,hi; unpack2(acc[j][k2],lo,hi);
                int mloc = (k2<2)? mi*4+2*k2 : 64+mi*4+2*(k2-2);
                int mq = mloc & 31;
                int r = qt*128 + mloc;
                if (vc){
                    unsigned long long kl=packkey(lo,gcol);
                    unsigned long long kh=packkey(hi,gcol);
                    if (kl>rk[2*k2])   rk[2*k2]=kl;
                    if (kh>rk[2*k2+1]) rk[2*k2+1]=kh;
                    if (r < QROWS){
                        if (mq < HWN){
                            unsigned long long kq=packkey(lo,(unsigned)mq);
                            if (k2<2){ if (kq>keyA) keyA=kq; } else { if (kq>keyB) keyB=kq; }
                        }
                        if (mq+1 < HWN){
                            unsigned long long kq=packkey(hi,(unsigned)(mq+1));
                            if (k2<2){ if (kq>keyA) keyA=kq; } else { if (kq>keyB) keyB=kq; }
                        }
                    }
                }
            }
            #pragma unroll
            for (int off=8;off<=16;off<<=1){
                unsigned long long oA=__shfl_xor_sync(0xffffffffu,keyA,off);
                unsigned long long oB=__shfl_xor_sync(0xffffffffu,keyB,off);
                if (oA>keyA) keyA=oA;
                if (oB>keyB) keyB=oB;
            }
            if (lane<8){
                if (keyA) atomicMax(&smq[gA*128 + coll], keyA);
                if (keyB) atomicMax(&smq[(2+gA)*128 + coll], keyB);
            }
        }
    }
    #pragma unroll
    for (int sdx=0;sdx<8;++sdx){
        unsigned long long v=rk[sdx];
        #pragma unroll
        for (int off=1;off<=4;off<<=1){
            unsigned long long o=__shfl_xor_sync(0xffffffffu,v,off);
            if (o>v) v=o;
        }
        if ((lane&7)==0 && v){
            int mloc = (sdx<4)? mi*4+sdx : 64+mi*4+(sdx-4);
            int r = qt*128+mloc;
            int mq = mloc & 31;
            if (r<QROWS && mq<HWN)
                atomicMax(&g_rowq[((size_t)b*QROWP + r)*NWAY + w], v);
        }
    }
    __syncthreads();
    int jg = ct*128 + tid;
    if (jg < wl){
        #pragma unroll
        for (int g=0; g<4; ++g){
            int q = qt*4 + g;
            if (q < QQ){
                unsigned long long k = smq[g*128+tid];
                unsigned mq = 0xFFFFFFFFu - (unsigned)(k & 0xFFFFFFFFu);
                g_colmq[(((size_t)b*QQ+q)*NWAY+w)*MTOT + jg] = (unsigned char)mq;
            }
        }
    }
}

// ---------------- K5: finish = mutual mask + CE loss per (b,q) ----------------
__global__ void k_fin(const int* __restrict__ qy, float* __restrict__ out){
    int q=blockIdx.x, b=blockIdx.y;
    int lane=threadIdx.x;
    int sL=g_L[0];
    int cnt[NWAY];
    #pragma unroll
    for (int w=0;w<NWAY;++w) cnt[w]=g_count[b*NWAY+w];
    float rmx[NWAY]={0.f,0.f,0.f,0.f,0.f};
    unsigned long long qb=0ULL;
    float maskv=0.f;
    if (lane < HWN){
        #pragma unroll
        for (int w=0;w<NWAY;++w){
            unsigned long long r = g_rowq[((size_t)b*QROWP + q*32 + lane)*NWAY + w];
            if (cnt[w] < sL){
                unsigned long long pk = packkey(0.0f,(unsigned)(w*MTOT+MS+cnt[w]));
                if (pk>r) r=pk;
            }
            rmx[w]=fmaf(funmap((unsigned)(r>>32)),0.5f,0.5f);
            if (r>qb) qb=r;
        }
        unsigned gcol = 0xFFFFFFFFu - (unsigned)(qb & 0xFFFFFFFFu);
        int w_ = (int)(gcol / MTOT), j_ = (int)(gcol % MTOT);
        int amq = (j_ < MS+cnt[w_]) ? (int)g_colmq[(((size_t)b*QQ+q)*NWAY+w_)*MTOT + j_] : 0;
        maskv = (amq==lane) ? 1.f : 0.f;
    }
    float qv[NWAY];
    #pragma unroll
    for (int w=0;w<NWAY;++w){
        float t = (lane<HWN) ? rmx[w]*maskv : 0.f;
        #pragma unroll
        for (int off=16;off>=1;off>>=1) t += __shfl_xor_sync(0xffffffffu,t,off);
        qv[w]=t;
    }
    if (lane==0){
        int y = qy[b*QQ+q];
        float mx=qv[0];
        #pragma unroll
        for (int w=1;w<NWAY;++w) mx=fmaxf(mx,qv[w]);
        float se=0.f;
        #pragma unroll
        for (int w=0;w<NWAY;++w) se += expf(qv[w]-mx);
        float li = mx + logf(se) - qv[y];
        atomicAdd(out, li*(1.0f/(float)(BB*QQ)));
    }
}

// ---------------- launch ----------------
extern "C" void kernel_launch(void* const* d_in, const int* in_sizes, int n_in,
                              void* d_out, int out_size) {
    const float* sup = nullptr;
    const float* qx  = nullptr;
    const float* ux  = nullptr;
    const int*   qy  = nullptr;
    for (int i=0;i<n_in;++i){
        switch (in_sizes[i]){
            case 160000: sup = (const float*)d_in[i]; break; // support_xf
            case 480000: qx  = (const float*)d_in[i]; break; // query_xf
            case 640000: ux  = (const float*)d_in[i]; break; // unlabeled_xf
            case 300:    qy  = (const int*)d_in[i];   break; // query_y
            default: break;                                  // support_y unused
        }
    }
    float* out = (float*)d_out;
    k_prep<<<816,256>>>(sup, ux, qx, out, out_size);
    k_u2s<<<dim3(20,5,BB),128>>>();
    k_compact<<<BB*NWAY,256>>>();
    k_gather<<<dim3(BB*NWAY,CC),256>>>();
    k_qsim<<<dim3(21,19,BB*NWAY),128>>>();
    k_fin<<<dim3(QQ,BB),32>>>(qy, out);
}

// round 6
// speedup vs baseline: 2.7897x; 1.0801x over previous
#include <cuda_runtime.h>
#include <math.h>

#define NWAY 5
#define BB 4
#define CC 64
#define HWN 25
#define MS 125      // K_SHOT * h * w
#define MU 2500     // u * h * w
#define QQ 75
#define COLS 625    // NWAY * MS
#define MTOT 2625   // MS + MU
#define COLP 640    // padded cols for transposed support
#define MUP 2560    // padded m for transposed unlabeled
#define QROWS 1875  // 75 q * 25 rows (packed)
#define QROWP 1920  // padded to 15*128
#define CATP 2688   // padded cat columns (21*128)

// ---------------- scratch (static device allocations only) ----------------
__device__ float g_sup_t[BB*CC*COLP];            // [b][c][col] transposed support (pad zeroed)
__device__ float g_unl_t[BB*CC*MUP];             // [b][c][m]   transposed unlabeled (pad zeroed)
__device__ float g_q_t[BB*CC*QROWP];             // [b][c][q*25+mq] transposed query (pads zero)
__device__ float g_cat_t[BB*NWAY*CC*CATP];       // [bw][c][j] = [sup(125) | compacted unl(cw)]
__device__ unsigned long long g_rowbest[BB*MU];  // per (b,m): packed (val,col) argmax
__device__ unsigned long long g_colbest[BB*COLS];// per (b,col): packed (val,m) argmax
__device__ unsigned long long g_rowq[BB*QROWP*NWAY]; // per (b,row,w): packed best over cols
__device__ int g_sel[BB*NWAY*MU];                // compacted m-indices per (b,way)
__device__ int g_count[BB*NWAY];
__device__ int g_L[1];

// monotone float ordering map (handles negatives exactly)
__device__ __forceinline__ unsigned fmap(float f){
    unsigned b=__float_as_uint(f);
    return (b&0x80000000u)? ~b : (b|0x80000000u);
}
__device__ __forceinline__ float funmap(unsigned u){
    return (u&0x80000000u)? __uint_as_float(u^0x80000000u) : __uint_as_float(~u);
}
// max-value, min-index-on-tie key (matches jnp first-occurrence argmax)
__device__ __forceinline__ unsigned long long packkey(float v, unsigned idx){
    return (((unsigned long long)fmap(v))<<32) | (unsigned long long)(0xFFFFFFFFu - idx);
}
// packed 2xFP32 FMA (Blackwell f32x2)
__device__ __forceinline__ void fma2(unsigned long long& acc, unsigned long long a, unsigned long long b){
    asm("fma.rn.f32x2 %0, %1, %2, %0;" : "+l"(acc) : "l"(a), "l"(b));
}
__device__ __forceinline__ unsigned long long splat2(float x){
    unsigned long long r;
    asm("mov.b64 %0, {%1, %1};" : "=l"(r) : "r"(__float_as_uint(x)));
    return r;
}
__device__ __forceinline__ void unpack2(unsigned long long v, float& lo, float& hi){
    unsigned a,b;
    asm("mov.b64 {%0, %1}, %2;" : "=r"(a), "=r"(b) : "l"(v));
    lo=__uint_as_float(a); hi=__uint_as_float(b);
}

// ---------------- K0: prep = init + all normalizations ----------------
__global__ void __launch_bounds__(256) k_prep(const float* __restrict__ sup,
                                              const float* __restrict__ unl,
                                              const float* __restrict__ qx,
                                              float* __restrict__ out, int out_size){
    int s = blockIdx.x;
    int tid = threadIdx.x;
    if (s >= 800){
        int i = (s-800)*256 + tid;
        const int stride = 16*256;
        for (int t=i;t<BB*MU;t+=stride) g_rowbest[t]=0ULL;
        for (int t=i;t<BB*COLS;t+=stride) g_colbest[t]=0ULL;
        for (int t=i;t<BB*QROWP*NWAY;t+=stride) g_rowq[t]=0ULL;
        for (int t=i;t<BB*CC*(COLP-COLS);t+=stride){
            int bc=t/(COLP-COLS), p=t%(COLP-COLS);
            g_sup_t[(size_t)bc*COLP+COLS+p]=0.f;
        }
        for (int t=i;t<BB*CC*(MUP-MU);t+=stride){
            int bc=t/(MUP-MU), p=t%(MUP-MU);
            g_unl_t[(size_t)bc*MUP+MU+p]=0.f;
        }
        // pad rows 1875..1919 of g_q_t
        for (int t=i;t<BB*CC*(QROWP-QROWS);t+=stride){
            int bc=t/(QROWP-QROWS), p=t%(QROWP-QROWS);
            g_q_t[(size_t)bc*QROWP+QROWS+p]=0.f;
        }
        if (i==0) g_L[0]=0;
        for (int t=i;t<out_size;t+=stride) out[t]=0.f;
        return;
    }
    __shared__ float tile[1600];
    __shared__ float inv[HWN];
    const float* in;
    if (s<100)      in = sup + (size_t)s*1600;
    else if (s<500) in = unl + (size_t)(s-100)*1600;
    else            in = qx  + (size_t)(s-500)*1600;
    for (int t=tid;t<1600;t+=256) tile[t]=in[t];
    __syncthreads();
    if (tid<HWN){
        float a=0.f;
        for (int c=0;c<CC;++c){ float v=tile[c*HWN+tid]; a=fmaf(v,v,a); }
        inv[tid]=1.0f/fmaxf(sqrtf(a),1e-12f);
    }
    __syncthreads();
    if (s<100){
        int b=s/25, sk=s%25, w=sk/5, k=sk%5;
        int colbase=w*MS+k*25;
        float* outt=g_sup_t+(size_t)b*CC*COLP+colbase;
        for (int o=tid;o<1600;o+=256){ int c=o/HWN,hw=o%HWN; outt[(size_t)c*COLP+hw]=tile[o]*inv[hw]; }
    } else if (s<500){
        int t2=s-100; int b=t2/100,u=t2%100;
        float* outt=g_unl_t+(size_t)b*CC*MUP+u*25;
        for (int o=tid;o<1600;o+=256){ int c=o/HWN,hw=o%HWN; outt[(size_t)c*MUP+hw]=tile[o]*inv[hw]; }
    } else {
        int t2=s-500; int b=t2/QQ, q=t2%QQ;
        float* outt=g_q_t+(size_t)b*CC*QROWP + q*25;
        for (int o=tid;o<1600;o+=256){ int c=o/HWN,hw=o%HWN; outt[(size_t)c*QROWP+hw]=tile[o]*inv[hw]; }
    }
}

// ---------------- K1: u2s GEMM (f32x2) + packed row/col argmax ----------------
__global__ void __launch_bounds__(128,3) k_u2s(){
    __shared__ float4 s4[2048];                  // [c][32 f4] = 128 cols (32KB)
    __shared__ float4 u4[2048];                  // [c][32 f4] = 128 m   (32KB)
    __shared__ unsigned long long sm_col[128];
    int mt=blockIdx.x, cp=blockIdx.y, b=blockIdx.z;
    int tid=threadIdx.x, lane=tid&31;
    int ci=tid&7, mi=tid>>3;

    const float4* gs4=(const float4*)g_sup_t + (size_t)b*(CC*COLP/4) + cp*32;
    #pragma unroll
    for (int t=0;t<16;++t){
        int idx=tid+t*128; int c=idx>>5, x=idx&31;
        s4[idx]=gs4[(size_t)c*(COLP/4)+x];
    }
    const float4* gu4=(const float4*)g_unl_t + (size_t)b*(CC*MUP/4) + mt*32;
    #pragma unroll
    for (int t=0;t<16;++t){
        int idx=tid+t*128; int c=idx>>5, x=idx&31;
        u4[idx]=gu4[(size_t)c*(MUP/4)+x];
    }
    sm_col[tid]=0ULL;
    __syncthreads();

    unsigned long long rk[8];
    #pragma unroll
    for (int sdx=0;sdx<8;++sdx) rk[sdx]=0ULL;

    #pragma unroll 1
    for (int h=0; h<2; ++h){
        unsigned long long acc[8][4];
        #pragma unroll
        for (int j=0;j<8;++j)
            #pragma unroll
            for (int k2=0;k2<4;++k2) acc[j][k2]=0ULL;

        #pragma unroll 2
        for (int c=0;c<64;++c){
            float4 a0=s4[c*32+h*16+ci];
            float4 a1=s4[c*32+h*16+8+ci];
            ulonglong2 bb0=*(const ulonglong2*)&u4[c*32+mi];
            ulonglong2 bb1=*(const ulonglong2*)&u4[c*32+16+mi];
            unsigned long long pb0=bb0.x, pb1=bb0.y, pb2=bb1.x, pb3=bb1.y;
            float av[8]={a0.x,a0.y,a0.z,a0.w,a1.x,a1.y,a1.z,a1.w};
            #pragma unroll
            for (int j=0;j<8;++j){
                unsigned long long sa=splat2(av[j]);
                fma2(acc[j][0],sa,pb0);
                fma2(acc[j][1],sa,pb1);
                fma2(acc[j][2],sa,pb2);
                fma2(acc[j][3],sa,pb3);
            }
        }
        #pragma unroll
        for (int j=0;j<8;++j){
            int colj = cp*128 + h*64 + ((j<4)? ci*4+j : 32+ci*4+(j-4));
            bool vc = colj < COLS;
            unsigned long long ck=0ULL;
            #pragma unroll
            for (int k2=0;k2<4;++k2){
                float lo,hi; unpack2(acc[j][k2],lo,hi);
                int mloc = (k2<2)? mi*4+2*k2 : 64+mi*4+2*(k2-2);
                int mglo = mt*128+mloc, mghi = mglo+1;
                if (vc){
                    unsigned long long kl=packkey(lo,(unsigned)colj);
                    unsigned long long kh=packkey(hi,(unsigned)colj);
                    if (kl>rk[2*k2])   rk[2*k2]=kl;
                    if (kh>rk[2*k2+1]) rk[2*k2+1]=kh;
                    if (mglo<MU){ unsigned long long c1=packkey(lo,(unsigned)mglo); if (c1>ck) ck=c1; }
                    if (mghi<MU){ unsigned long long c2=packkey(hi,(unsigned)mghi); if (c2>ck) ck=c2; }
                }
            }
            #pragma unroll
            for (int off=8;off<=16;off<<=1){
                unsigned long long o=__shfl_xor_sync(0xffffffffu,ck,off);
                if (o>ck) ck=o;
            }
            if (lane<8 && ck){
                int local = h*64 + ((j<4)? lane*4+j : 32+lane*4+(j-4));
                atomicMax(&sm_col[local], ck);
            }
        }
    }
    #pragma unroll
    for (int sdx=0;sdx<8;++sdx){
        unsigned long long v=rk[sdx];
        #pragma unroll
        for (int off=1;off<=4;off<<=1){
            unsigned long long o=__shfl_xor_sync(0xffffffffu,v,off);
            if (o>v) v=o;
        }
        if ((lane&7)==0 && v){
            int mloc = (sdx<4)? mi*4+sdx : 64+mi*4+(sdx-4);
            int mg = mt*128+mloc;
            if (mg<MU) atomicMax(&g_rowbest[(size_t)b*MU+mg], v);
        }
    }
    __syncthreads();
    if ((cp*128+tid)<COLS && sm_col[tid])
        atomicMax(&g_colbest[(size_t)b*COLS+cp*128+tid], sm_col[tid]);
}

// ---------------- K2: umask + stable stream compaction + L ----------------
__global__ void k_compact(){
    int bw = blockIdx.x; int b = bw/NWAY, w = bw%NWAY;
    int tid = threadIdx.x, lane = tid&31, wid = tid>>5;
    __shared__ int wsum[8], woff[8], sbase;
    if (tid==0) sbase=0;
    __syncthreads();
    for (int chunk=0; chunk<10; ++chunk){
        int m = chunk*256 + tid;
        bool flag = false;
        if (m < MU){
            unsigned long long rb = g_rowbest[b*MU+m];
            unsigned col = 0xFFFFFFFFu - (unsigned)(rb & 0xFFFFFFFFu);
            if ((int)(col/MS) == w){
                unsigned long long cb = g_colbest[b*COLS+col];
                unsigned mm = 0xFFFFFFFFu - (unsigned)(cb & 0xFFFFFFFFu);
                flag = (mm == (unsigned)m);
            }
        }
        unsigned bal = __ballot_sync(0xffffffffu, flag);
        if (lane==0) wsum[wid] = __popc(bal);
        __syncthreads();
        if (tid==0){
            int run=sbase;
            for (int i=0;i<8;++i){ woff[i]=run; run+=wsum[i]; }
            sbase=run;
        }
        __syncthreads();
        if (flag){
            int pos = woff[wid] + __popc(bal & ((1u<<lane)-1u));
            g_sel[(b*NWAY+w)*MU + pos] = m;
        }
        __syncthreads();
    }
    if (tid==0){
        g_count[b*NWAY+w] = sbase;
        atomicMax(&g_L[0], sbase);
    }
}

// ---------------- K3: gather concatenated transposed columns per (bw, c) ----
__global__ void __launch_bounds__(256) k_gather(){
    int bw = blockIdx.x; int c = blockIdx.y;
    int b = bw/NWAY, w = bw%NWAY;
    int cw = g_count[bw];
    const int* __restrict__ sel = g_sel + (size_t)bw*MU;
    float* __restrict__ dst = g_cat_t + ((size_t)bw*CC+c)*CATP;
    const float* __restrict__ ssrc = g_sup_t + ((size_t)b*CC+c)*COLP + w*MS;
    const float* __restrict__ usrc = g_unl_t + ((size_t)b*CC+c)*MUP;
    int tid = threadIdx.x;
    for (int j=tid;j<MS;j+=256) dst[j]=ssrc[j];
    for (int j=tid;j<cw;j+=256) dst[MS+j]=usrc[__ldg(&sel[j])];
}

// ---------------- K4: query GEMM (f32x2) + row-best epilogue ----------------
__global__ void __launch_bounds__(128,3) k_qsim(){
    int ct=blockIdx.x, qt=blockIdx.y, bw=blockIdx.z;
    int b=bw/NWAY, w=bw%NWAY;
    int cw=g_count[bw]; int wl=MS+cw;
    if (ct*128 >= wl) return;
    __shared__ float4 a4[2048];                 // q-rows: [c][32 f4] = 128 rows (32KB)
    __shared__ float4 v4[2048];                 // cols:   [c][32 f4] = 128 cols (32KB)
    int tid=threadIdx.x, lane=tid&31;
    int ci=tid&7, mi=tid>>3;

    const float4* ga=(const float4*)g_q_t + (size_t)b*(CC*QROWP/4) + qt*32;
    #pragma unroll
    for (int t=0;t<16;++t){
        int idx=tid+t*128; int c=idx>>5, x=idx&31;
        a4[idx]=ga[(size_t)c*(QROWP/4)+x];
    }
    const float4* gv=(const float4*)g_cat_t + (size_t)bw*(CC*CATP/4) + ct*32;
    #pragma unroll
    for (int t=0;t<16;++t){
        int idx=tid+t*128; int c=idx>>5, x=idx&31;
        v4[idx]=gv[(size_t)c*(CATP/4)+x];
    }
    __syncthreads();

    unsigned long long rk[8];
    #pragma unroll
    for (int sdx=0;sdx<8;++sdx) rk[sdx]=0ULL;

    #pragma unroll 1
    for (int h=0; h<2; ++h){
        unsigned long long acc[8][4];
        #pragma unroll
        for (int j=0;j<8;++j)
            #pragma unroll
            for (int k2=0;k2<4;++k2) acc[j][k2]=0ULL;

        #pragma unroll 2
        for (int c=0;c<64;++c){
            float4 a0=v4[c*32+h*16+ci];
            float4 a1=v4[c*32+h*16+8+ci];
            ulonglong2 bb0=*(const ulonglong2*)&a4[c*32+mi];
            ulonglong2 bb1=*(const ulonglong2*)&a4[c*32+16+mi];
            unsigned long long pb0=bb0.x, pb1=bb0.y, pb2=bb1.x, pb3=bb1.y;
            float av[8]={a0.x,a0.y,a0.z,a0.w,a1.x,a1.y,a1.z,a1.w};
            #pragma unroll
            for (int j=0;j<8;++j){
                unsigned long long sa=splat2(av[j]);
                fma2(acc[j][0],sa,pb0);
                fma2(acc[j][1],sa,pb1);
                fma2(acc[j][2],sa,pb2);
                fma2(acc[j][3],sa,pb3);
            }
        }
        #pragma unroll
        for (int j=0;j<8;++j){
            int coll = h*64 + ((j<4)? ci*4+j : 32+ci*4+(j-4));
            int jg = ct*128 + coll;
            if (jg < wl){
                unsigned gcol = (unsigned)(w*MTOT + jg);
                #pragma unroll
                for (int k2=0;k2<4;++k2){
                    float lo,hi; unpack2(acc[j][k2],lo,hi);
                    unsigned long long kl=packkey(lo,gcol);
                    unsigned long long kh=packkey(hi,gcol);
                    if (kl>rk[2*k2])   rk[2*k2]=kl;
                    if (kh>rk[2*k2+1]) rk[2*k2+1]=kh;
                }
            }
        }
    }
    #pragma unroll
    for (int sdx=0;sdx<8;++sdx){
        unsigned long long v=rk[sdx];
        #pragma unroll
        for (int off=1;off<=4;off<<=1){
            unsigned long long o=__shfl_xor_sync(0xffffffffu,v,off);
            if (o>v) v=o;
        }
        if ((lane&7)==0 && v){
            int mloc = (sdx<4)? mi*4+sdx : 64+mi*4+(sdx-4);
            int r = qt*128+mloc;
            if (r<QROWS)
                atomicMax(&g_rowq[((size_t)b*QROWP + r)*NWAY + w], v);
        }
    }
}

// ---------------- K5: finish = recompute col-argmax + mutual mask + CE ------
__global__ void __launch_bounds__(256) k_fin(const int* __restrict__ qy,
                                             float* __restrict__ out){
    int q=blockIdx.x, b=blockIdx.y;
    int tid=threadIdx.x, lane=tid&31, wp=tid>>5;
    __shared__ float rmx_s[NWAY][32];
    __shared__ unsigned gcol_s[32];
    __shared__ float mask_s[32];
    __shared__ int cnt_s[NWAY+1];
    if (tid<NWAY) cnt_s[tid]=g_count[b*NWAY+tid];
    if (tid==NWAY) cnt_s[NWAY]=g_L[0];
    if (tid<32) mask_s[tid]=0.f;
    __syncthreads();
    // stage 1: per-row (mq) way-maxes and global best column
    if (wp==0 && lane<HWN){
        unsigned long long qb=0ULL;
        #pragma unroll
        for (int w=0;w<NWAY;++w){
            unsigned long long r = g_rowq[((size_t)b*QROWP + q*25 + lane)*NWAY + w];
            int cww=cnt_s[w];
            if (cww < cnt_s[NWAY]){
                // first all-zero pad column of this way: raw cos = 0.0, col id MS+cww
                unsigned long long pk = packkey(0.0f,(unsigned)(w*MTOT+MS+cww));
                if (pk>r) r=pk;
            }
            rmx_s[w][lane]=fmaf(funmap((unsigned)(r>>32)),0.5f,0.5f);
            if (r>qb) qb=r;
        }
        gcol_s[lane]=0xFFFFFFFFu - (unsigned)(qb & 0xFFFFFFFFu);
    }
    __syncthreads();
    // stage 2: per winning column, recompute argmax over mq (bitwise-identical chain)
    for (int t=wp; t<HWN; t+=8){
        unsigned gcol=gcol_s[t];
        int w_=(int)(gcol/MTOT), j_=(int)(gcol%MTOT);
        int amq=0;
        if (j_ < MS + cnt_s[w_]){
            float acc=0.f;
            const float* qp = g_q_t + (size_t)b*CC*QROWP + q*25 + lane;
            const float* cp = g_cat_t + (size_t)(b*NWAY+w_)*CC*CATP + j_;
            if (lane<HWN){
                #pragma unroll
                for (int c=0;c<CC;++c)
                    acc=fmaf(qp[(size_t)c*QROWP], cp[(size_t)c*CATP], acc);
            }
            unsigned long long k = (lane<HWN)? packkey(acc,(unsigned)lane) : 0ULL;
            #pragma unroll
            for (int off=16;off>=1;off>>=1){
                unsigned long long o=__shfl_xor_sync(0xffffffffu,k,off);
                if (o>k) k=o;
            }
            amq = (int)(0xFFFFFFFFu - (unsigned)(k & 0xFFFFFFFFu));
        }
        if (lane==0) mask_s[t] = (amq==t)?1.f:0.f;
    }
    __syncthreads();
    // stage 3: qv + cross-entropy
    if (wp==0){
        float qv[NWAY];
        #pragma unroll
        for (int w=0;w<NWAY;++w){
            float t = (lane<HWN) ? rmx_s[w][lane]*mask_s[lane] : 0.f;
            #pragma unroll
            for (int off=16;off>=1;off>>=1) t += __shfl_xor_sync(0xffffffffu,t,off);
            qv[w]=t;
        }
        if (lane==0){
            int y = qy[b*QQ+q];
            float mx=qv[0];
            #pragma unroll
            for (int w=1;w<NWAY;++w) mx=fmaxf(mx,qv[w]);
            float se=0.f;
            #pragma unroll
            for (int w=0;w<NWAY;++w) se += expf(qv[w]-mx);
            float li = mx + logf(se) - qv[y];
            atomicAdd(out, li*(1.0f/(float)(BB*QQ)));
        }
    }
}

// ---------------- launch ----------------
extern "C" void kernel_launch(void* const* d_in, const int* in_sizes, int n_in,
                              void* d_out, int out_size) {
    const float* sup = nullptr;
    const float* qx  = nullptr;
    const float* ux  = nullptr;
    const int*   qy  = nullptr;
    for (int i=0;i<n_in;++i){
        switch (in_sizes[i]){
            case 160000: sup = (const float*)d_in[i]; break; // support_xf
            case 480000: qx  = (const float*)d_in[i]; break; // query_xf
            case 640000: ux  = (const float*)d_in[i]; break; // unlabeled_xf
            case 300:    qy  = (const int*)d_in[i];   break; // query_y
            default: break;                                  // support_y unused
        }
    }
    float* out = (float*)d_out;
    k_prep<<<816,256>>>(sup, ux, qx, out, out_size);
    k_u2s<<<dim3(20,5,BB),128>>>();
    k_compact<<<BB*NWAY,256>>>();
    k_gather<<<dim3(BB*NWAY,CC),256>>>();
    k_qsim<<<dim3(21,15,BB*NWAY),128>>>();
    k_fin<<<dim3(QQ,BB),256>>>(qy, out);
}